// round 8
// baseline (speedup 1.0000x reference)
#include <cuda_runtime.h>
#include <cuda_fp16.h>
#include <cstdint>
#include <cstddef>

// ---------------------------------------------------------------------------
// WL2 graph conv layer — tf32 mma.sync GEMMs (32-row warp tiles) +
// counting-sorted gather conv + side-stream overlap of the edge sort.
//   main stream : prep_w -> gemm_xwn ----------------\
//   side stream : hist -> scan -> scatter ------------+-> conv_row -> gemm_final
// ---------------------------------------------------------------------------

#define NMAX   200000
#define MEDGE  2000000
#define HPAD   200704              // 196 * 1024 (padded histogram length)
#define NBLK   196                 // scan blocks of 1024
#define MAXELEMS ((size_t)NMAX * 128)

__device__ __half g_xwnh[MAXELEMS];      // fp16 neighbor projection
__device__ float  g_conv[MAXELEMS];      // conv rows (written once, no atomics)
__device__ float  g_wt[3 * 128 * 128];   // W^T (K-major), tf32-rounded

__device__ int  g_hist[HPAD];
__device__ int  g_rowscan[HPAD];
__device__ int  g_bsum[NBLK];
__device__ int  g_bsumoff[NBLK];
__device__ int  g_rowstart[NMAX + 1];
__device__ int  g_cursor[NMAX];
__device__ int2 g_sab[MEDGE];            // sorted (ref_a, ref_b) pairs

// ---------------- helpers ----------------
__device__ __forceinline__ uint32_t f2tf32(float x) {
    uint32_t r;
    asm("cvt.rna.tf32.f32 %0, %1;" : "=r"(r) : "f"(x));
    return r;
}

__device__ __forceinline__ uint32_t smem_u32(const void* p) {
    uint32_t a;
    asm("{ .reg .u64 t; cvta.to.shared.u64 t, %1; cvt.u32.u64 %0, t; }"
        : "=r"(a) : "l"(p));
    return a;
}

__device__ __forceinline__ void cp_async16(uint32_t dst, const void* src) {
    asm volatile("cp.async.ca.shared.global [%0], [%1], 16;"
                 :: "r"(dst), "l"(src) : "memory");
}
__device__ __forceinline__ void cp_commit() {
    asm volatile("cp.async.commit_group;" ::: "memory");
}
__device__ __forceinline__ void cp_wait1() {
    asm volatile("cp.async.wait_group 1;" ::: "memory");
}

__device__ __forceinline__ void mma_tf32(float* c,
                                         uint32_t a0, uint32_t a1, uint32_t a2, uint32_t a3,
                                         uint32_t b0, uint32_t b1) {
    asm volatile(
        "mma.sync.aligned.m16n8k8.row.col.f32.tf32.tf32.f32 "
        "{%0,%1,%2,%3}, {%4,%5,%6,%7}, {%8,%9}, {%0,%1,%2,%3};"
        : "+f"(c[0]), "+f"(c[1]), "+f"(c[2]), "+f"(c[3])
        : "r"(a0), "r"(a1), "r"(a2), "r"(a3), "r"(b0), "r"(b1));
}

#define TPITCH 132
#define TILE_FLOATS (128 * TPITCH)

// ---------------------------------------------------------------------------
// Phase 0: W^T + tf32 rounding
// ---------------------------------------------------------------------------
__global__ void prep_w_kernel(const float* __restrict__ Wl,
                              const float* __restrict__ Wf,
                              const float* __restrict__ Wn) {
    const float* src = (blockIdx.x == 0) ? Wl : ((blockIdx.x == 1) ? Wf : Wn);
    float* dst = g_wt + blockIdx.x * 16384;
    for (int i = threadIdx.x; i < 16384; i += blockDim.x) {
        int n = i >> 7, k = i & 127;
        dst[i] = __uint_as_float(f2tf32(src[k * 128 + n]));
    }
}

// ---------------------------------------------------------------------------
// Phase 1 (side stream): counting sort of edges by backref
// ---------------------------------------------------------------------------
__global__ void hist_zero_kernel() {
    int i = blockIdx.x * 256 + threadIdx.x;
    if (i < HPAD) g_hist[i] = 0;
}

__global__ void hist_kernel(const int* __restrict__ br, int m) {
    for (int e = blockIdx.x * 256 + threadIdx.x; e < m; e += gridDim.x * 256)
        atomicAdd(&g_hist[__ldg(br + e)], 1);
}

__global__ void scan1_kernel() {
    __shared__ int wsum[8];
    const int t = threadIdx.x;
    const int base = blockIdx.x * 1024 + t * 4;
    const int4 v = *reinterpret_cast<const int4*>(g_hist + base);
    const int s1 = v.x + v.y, s2 = s1 + v.z, s3 = s2 + v.w;
    const int lane = t & 31, w = t >> 5;
    int x = s3;
#pragma unroll
    for (int d = 1; d < 32; d <<= 1) {
        int y = __shfl_up_sync(0xffffffffu, x, d);
        if (lane >= d) x += y;
    }
    if (lane == 31) wsum[w] = x;
    __syncthreads();
    if (t < 8) {
        int v2 = wsum[t];
#pragma unroll
        for (int d = 1; d < 8; d <<= 1) {
            int y = __shfl_up_sync(0xffu, v2, d);
            if (t >= d) v2 += y;
        }
        wsum[t] = v2;
    }
    __syncthreads();
    const int woff = w ? wsum[w - 1] : 0;
    const int excl = woff + x - s3;
    int4 o;
    o.x = excl; o.y = excl + v.x; o.z = excl + s1; o.w = excl + s2;
    *reinterpret_cast<int4*>(g_rowscan + base) = o;
    if (t == 255) g_bsum[blockIdx.x] = wsum[7];
}

__global__ void scan2_kernel() {
    __shared__ int wsum[8];
    const int t = threadIdx.x;
    const int v = (t < NBLK) ? g_bsum[t] : 0;
    const int lane = t & 31, w = t >> 5;
    int x = v;
#pragma unroll
    for (int d = 1; d < 32; d <<= 1) {
        int y = __shfl_up_sync(0xffffffffu, x, d);
        if (lane >= d) x += y;
    }
    if (lane == 31) wsum[w] = x;
    __syncthreads();
    if (t < 8) {
        int v2 = wsum[t];
#pragma unroll
        for (int d = 1; d < 8; d <<= 1) {
            int y = __shfl_up_sync(0xffu, v2, d);
            if (t >= d) v2 += y;
        }
        wsum[t] = v2;
    }
    __syncthreads();
    const int woff = w ? wsum[w - 1] : 0;
    if (t < NBLK) g_bsumoff[t] = woff + x - v;
}

__global__ void scan3_kernel(int n, int m) {
    const int i = blockIdx.x * 256 + threadIdx.x;
    if (i < n) {
        const int val = g_rowscan[i] + g_bsumoff[i >> 10];
        g_rowstart[i] = val;
        g_cursor[i] = val;
    }
    if (i == 0) g_rowstart[n] = m;
}

__global__ void scatter_kernel(const int* __restrict__ ra,
                               const int* __restrict__ rb,
                               const int* __restrict__ br, int m) {
    const int e = blockIdx.x * 256 + threadIdx.x;
    if (e >= m) return;
    const int c = __ldg(br + e);
    const int p = atomicAdd(&g_cursor[c], 1);
    g_sab[p] = make_int2(__ldg(ra + e), __ldg(rb + e));
}

// ---------------------------------------------------------------------------
// B-tile loader (raw fp32, already tf32-rounded in g_wt) — 256 threads
// ---------------------------------------------------------------------------
__device__ __forceinline__ void load_b_tile(float* Bs, const float* __restrict__ Wt,
                                            int tid) {
    for (int i = tid; i < 4096; i += 256) {
        const int r = i >> 5, c4 = i & 31;
        float4 v = reinterpret_cast<const float4*>(Wt)[i];
        *reinterpret_cast<float4*>(&Bs[r * TPITCH + c4 * 4]) = v;
    }
}

// ---------------------------------------------------------------------------
// Phase 2: XW_n = X @ W_n, persistent, 256 threads, warp tile 32x64.
// 8 warps: m-group = wid&3 (32 rows), n-group = wid>>2 (64 cols).
// ---------------------------------------------------------------------------
#define XC_ROWS 128
#define XC_FLOATS (XC_ROWS * TPITCH)

__global__ __launch_bounds__(256, 1)
void gemm_xwn_kernel(const float* __restrict__ X, int nrows) {
    extern __shared__ __align__(16) float smem[];
    float* Bs = smem;
    float* Ab[2] = { smem + TILE_FLOATS, smem + TILE_FLOATS + XC_FLOATS };
    const uint32_t sb = smem_u32(smem);
    const uint32_t aoff[2] = { (uint32_t)(TILE_FLOATS * 4),
                               (uint32_t)((TILE_FLOATS + XC_FLOATS) * 4) };

    const int tid = threadIdx.x;
    const int ntiles = (nrows + XC_ROWS - 1) / XC_ROWS;
    const int stride = gridDim.x;

    load_b_tile(Bs, g_wt + 2 * 16384, tid);

    int tile0 = blockIdx.x;
    if (tile0 < ntiles) {
#pragma unroll
        for (int j = 0; j < 16; j++) {
            const int i = tid + j * 256;
            const int r = i >> 5, c4 = i & 31;
            const int gr = tile0 * XC_ROWS + r;
            if (gr < nrows)
                cp_async16(sb + aoff[0] + (uint32_t)(r * TPITCH + c4 * 4) * 4,
                           X + (size_t)gr * 128 + c4 * 4);
        }
    }
    cp_commit();

    const int wid = tid >> 5, lane = tid & 31;
    const int g = lane >> 2, t = lane & 3;
    const int m_base = (wid & 3) * 32;
    const int n_base = (wid >> 2) * 64;

    int buf = 0;
    for (int tile = tile0; tile < ntiles; tile += stride, buf ^= 1) {
        const int nxt = tile + stride;
        if (nxt < ntiles) {
#pragma unroll
            for (int j = 0; j < 16; j++) {
                const int i = tid + j * 256;
                const int r = i >> 5, c4 = i & 31;
                const int gr = nxt * XC_ROWS + r;
                if (gr < nrows)
                    cp_async16(sb + aoff[buf ^ 1] + (uint32_t)(r * TPITCH + c4 * 4) * 4,
                               X + (size_t)gr * 128 + c4 * 4);
            }
        }
        cp_commit();
        cp_wait1();
        __syncthreads();

        const float* As = Ab[buf];
        float acc[2][8][4];
#pragma unroll
        for (int h = 0; h < 2; h++)
#pragma unroll
            for (int nt = 0; nt < 8; nt++)
#pragma unroll
                for (int j = 0; j < 4; j++) acc[h][nt][j] = 0.f;

        const float* ar = &As[(m_base + g) * TPITCH + t];
        const float* br = &Bs[(n_base + g) * TPITCH + t];

#pragma unroll
        for (int ks = 0; ks < 16; ks++) {
            const int k = ks * 8;
            const uint32_t a0 = f2tf32(ar[k]);
            const uint32_t a1 = f2tf32(ar[8 * TPITCH + k]);
            const uint32_t a2 = f2tf32(ar[k + 4]);
            const uint32_t a3 = f2tf32(ar[8 * TPITCH + k + 4]);
            const uint32_t a4 = f2tf32(ar[16 * TPITCH + k]);
            const uint32_t a5 = f2tf32(ar[24 * TPITCH + k]);
            const uint32_t a6 = f2tf32(ar[16 * TPITCH + k + 4]);
            const uint32_t a7 = f2tf32(ar[24 * TPITCH + k + 4]);
#pragma unroll
            for (int nt = 0; nt < 8; nt++) {
                const uint32_t b0 = __float_as_uint(br[nt * 8 * TPITCH + k]);
                const uint32_t b1 = __float_as_uint(br[nt * 8 * TPITCH + k + 4]);
                mma_tf32(acc[0][nt], a0, a1, a2, a3, b0, b1);
                mma_tf32(acc[1][nt], a4, a5, a6, a7, b0, b1);
            }
        }

#pragma unroll
        for (int h = 0; h < 2; h++) {
            const int r0 = tile * XC_ROWS + m_base + h * 16 + g;
            const int r1 = r0 + 8;
#pragma unroll
            for (int nt = 0; nt < 8; nt++) {
                const int col = n_base + nt * 8 + 2 * t;
                if (r0 < nrows)
                    *reinterpret_cast<__half2*>(g_xwnh + (size_t)r0 * 128 + col) =
                        __floats2half2_rn(acc[h][nt][0], acc[h][nt][1]);
                if (r1 < nrows)
                    *reinterpret_cast<__half2*>(g_xwnh + (size_t)r1 * 128 + col) =
                        __floats2half2_rn(acc[h][nt][2], acc[h][nt][3]);
            }
        }
        __syncthreads();
    }
}

// ---------------------------------------------------------------------------
// Phase 3: conv rows. One warp per row; gather edges, relu, register sum,
// single coalesced store.
// ---------------------------------------------------------------------------
__global__ __launch_bounds__(256)
void conv_row_kernel(const float* __restrict__ bn, int n) {
    const int wid = threadIdx.x >> 5, lane = threadIdx.x & 31;
    const int r = blockIdx.x * 8 + wid;
    if (r >= n) return;

    const int s0 = g_rowstart[r];
    const int s1 = g_rowstart[r + 1];
    const float4 bb = __ldg(reinterpret_cast<const float4*>(bn) + lane);

    float ax = 0.f, ay = 0.f, az = 0.f, aw = 0.f;

    int i = s0;
    for (; i + 2 <= s1; i += 2) {
        const int2 e0 = __ldg(g_sab + i);
        const int2 e1 = __ldg(g_sab + i + 1);
        const uint2 pa0 = *reinterpret_cast<const uint2*>(g_xwnh + (size_t)e0.x * 128 + lane * 4);
        const uint2 pb0 = *reinterpret_cast<const uint2*>(g_xwnh + (size_t)e0.y * 128 + lane * 4);
        const uint2 pa1 = *reinterpret_cast<const uint2*>(g_xwnh + (size_t)e1.x * 128 + lane * 4);
        const uint2 pb1 = *reinterpret_cast<const uint2*>(g_xwnh + (size_t)e1.y * 128 + lane * 4);
        {
            const float2 x01 = __half22float2(*reinterpret_cast<const __half2*>(&pa0.x));
            const float2 x23 = __half22float2(*reinterpret_cast<const __half2*>(&pa0.y));
            const float2 y01 = __half22float2(*reinterpret_cast<const __half2*>(&pb0.x));
            const float2 y23 = __half22float2(*reinterpret_cast<const __half2*>(&pb0.y));
            ax += fmaxf(x01.x + y01.x + bb.x, 0.f);
            ay += fmaxf(x01.y + y01.y + bb.y, 0.f);
            az += fmaxf(x23.x + y23.x + bb.z, 0.f);
            aw += fmaxf(x23.y + y23.y + bb.w, 0.f);
        }
        {
            const float2 x01 = __half22float2(*reinterpret_cast<const __half2*>(&pa1.x));
            const float2 x23 = __half22float2(*reinterpret_cast<const __half2*>(&pa1.y));
            const float2 y01 = __half22float2(*reinterpret_cast<const __half2*>(&pb1.x));
            const float2 y23 = __half22float2(*reinterpret_cast<const __half2*>(&pb1.y));
            ax += fmaxf(x01.x + y01.x + bb.x, 0.f);
            ay += fmaxf(x01.y + y01.y + bb.y, 0.f);
            az += fmaxf(x23.x + y23.x + bb.z, 0.f);
            aw += fmaxf(x23.y + y23.y + bb.w, 0.f);
        }
    }
    if (i < s1) {
        const int2 e0 = __ldg(g_sab + i);
        const uint2 pa0 = *reinterpret_cast<const uint2*>(g_xwnh + (size_t)e0.x * 128 + lane * 4);
        const uint2 pb0 = *reinterpret_cast<const uint2*>(g_xwnh + (size_t)e0.y * 128 + lane * 4);
        const float2 x01 = __half22float2(*reinterpret_cast<const __half2*>(&pa0.x));
        const float2 x23 = __half22float2(*reinterpret_cast<const __half2*>(&pa0.y));
        const float2 y01 = __half22float2(*reinterpret_cast<const __half2*>(&pb0.x));
        const float2 y23 = __half22float2(*reinterpret_cast<const __half2*>(&pb0.y));
        ax += fmaxf(x01.x + y01.x + bb.x, 0.f);
        ay += fmaxf(x01.y + y01.y + bb.y, 0.f);
        az += fmaxf(x23.x + y23.x + bb.z, 0.f);
        aw += fmaxf(x23.y + y23.y + bb.w, 0.f);
    }

    *reinterpret_cast<float4*>(g_conv + (size_t)r * 128 + lane * 4) =
        make_float4(ax, ay, az, aw);
}

// ---------------------------------------------------------------------------
// Phase 4: fused final dual GEMM + epilogue. 256 threads, warp tile 32x32
// (dual accumulators), 64-row chunks. 8 warps: m = wid&1, n = wid>>1.
// ---------------------------------------------------------------------------
#define FC_ROWS 64
#define FC_FLOATS (FC_ROWS * TPITCH)

__global__ __launch_bounds__(256, 1)
void gemm_final_kernel(const float* __restrict__ X, const float* __restrict__ b,
                       float* __restrict__ out, int nrows) {
    extern __shared__ __align__(16) float smem[];
    float* Bsl = smem;
    float* Bsf = smem + TILE_FLOATS;
    float* Ab[2] = { smem + 2 * TILE_FLOATS, smem + 2 * TILE_FLOATS + FC_FLOATS };
    const uint32_t sb = smem_u32(smem);
    const uint32_t aoff[2] = { (uint32_t)(2 * TILE_FLOATS * 4),
                               (uint32_t)((2 * TILE_FLOATS + FC_FLOATS) * 4) };

    const int tid = threadIdx.x;
    const int ntiles = (nrows + FC_ROWS - 1) / FC_ROWS;
    const int stride = gridDim.x;

    load_b_tile(Bsl, g_wt + 0 * 16384, tid);
    load_b_tile(Bsf, g_wt + 1 * 16384, tid);

    int tile0 = blockIdx.x;
    if (tile0 < ntiles) {
#pragma unroll
        for (int j = 0; j < 8; j++) {
            const int i = tid + j * 256;
            const int r = i >> 5, c4 = i & 31;
            const int gr = tile0 * FC_ROWS + r;
            if (gr < nrows)
                cp_async16(sb + aoff[0] + (uint32_t)(r * TPITCH + c4 * 4) * 4,
                           X + (size_t)gr * 128 + c4 * 4);
        }
    }
    cp_commit();

    const int wid = tid >> 5, lane = tid & 31;
    const int g = lane >> 2, t = lane & 3;
    const int m_base = (wid & 1) * 32;
    const int n_base = (wid >> 1) * 32;

    int buf = 0;
    for (int tile = tile0; tile < ntiles; tile += stride, buf ^= 1) {
        const int nxt = tile + stride;
        if (nxt < ntiles) {
#pragma unroll
            for (int j = 0; j < 8; j++) {
                const int i = tid + j * 256;
                const int r = i >> 5, c4 = i & 31;
                const int gr = nxt * FC_ROWS + r;
                if (gr < nrows)
                    cp_async16(sb + aoff[buf ^ 1] + (uint32_t)(r * TPITCH + c4 * 4) * 4,
                               X + (size_t)gr * 128 + c4 * 4);
            }
        }
        cp_commit();
        cp_wait1();
        __syncthreads();

        const float* As = Ab[buf];
        float accl[2][4][4], accf[2][4][4];
#pragma unroll
        for (int h = 0; h < 2; h++)
#pragma unroll
            for (int nt = 0; nt < 4; nt++)
#pragma unroll
                for (int j = 0; j < 4; j++) { accl[h][nt][j] = 0.f; accf[h][nt][j] = 0.f; }

        const float* ar  = &As[(m_base + g) * TPITCH + t];
        const float* brl = &Bsl[(n_base + g) * TPITCH + t];
        const float* brf = &Bsf[(n_base + g) * TPITCH + t];

#pragma unroll
        for (int ks = 0; ks < 16; ks++) {
            const int k = ks * 8;
            const uint32_t a0 = f2tf32(ar[k]);
            const uint32_t a1 = f2tf32(ar[8 * TPITCH + k]);
            const uint32_t a2 = f2tf32(ar[k + 4]);
            const uint32_t a3 = f2tf32(ar[8 * TPITCH + k + 4]);
            const uint32_t a4 = f2tf32(ar[16 * TPITCH + k]);
            const uint32_t a5 = f2tf32(ar[24 * TPITCH + k]);
            const uint32_t a6 = f2tf32(ar[16 * TPITCH + k + 4]);
            const uint32_t a7 = f2tf32(ar[24 * TPITCH + k + 4]);
#pragma unroll
            for (int nt = 0; nt < 4; nt++) {
                const uint32_t bl0 = __float_as_uint(brl[nt * 8 * TPITCH + k]);
                const uint32_t bl1 = __float_as_uint(brl[nt * 8 * TPITCH + k + 4]);
                mma_tf32(accl[0][nt], a0, a1, a2, a3, bl0, bl1);
                mma_tf32(accl[1][nt], a4, a5, a6, a7, bl0, bl1);
                const uint32_t bf0 = __float_as_uint(brf[nt * 8 * TPITCH + k]);
                const uint32_t bf1 = __float_as_uint(brf[nt * 8 * TPITCH + k + 4]);
                mma_tf32(accf[0][nt], a0, a1, a2, a3, bf0, bf1);
                mma_tf32(accf[1][nt], a4, a5, a6, a7, bf0, bf1);
            }
        }

#pragma unroll
        for (int h = 0; h < 2; h++) {
            const int r0 = tile * FC_ROWS + m_base + h * 16 + g;
            const int r1 = r0 + 8;
#pragma unroll
            for (int nt = 0; nt < 4; nt++) {
                const int col = n_base + nt * 8 + 2 * t;
                const float2 b2 = __ldg(reinterpret_cast<const float2*>(b + col));
                if (r0 < nrows) {
                    const float2 cv = *reinterpret_cast<const float2*>(g_conv + (size_t)r0 * 128 + col);
                    float2 o;
                    o.x = fmaxf(fmaf(accf[h][nt][0], cv.x, accl[h][nt][0]) + b2.x, 0.f);
                    o.y = fmaxf(fmaf(accf[h][nt][1], cv.y, accl[h][nt][1]) + b2.y, 0.f);
                    *reinterpret_cast<float2*>(out + (size_t)r0 * 128 + col) = o;
                }
                if (r1 < nrows) {
                    const float2 cv = *reinterpret_cast<const float2*>(g_conv + (size_t)r1 * 128 + col);
                    float2 o;
                    o.x = fmaxf(fmaf(accf[h][nt][2], cv.x, accl[h][nt][2]) + b2.x, 0.f);
                    o.y = fmaxf(fmaf(accf[h][nt][3], cv.y, accl[h][nt][3]) + b2.y, 0.f);
                    *reinterpret_cast<float2*>(out + (size_t)r1 * 128 + col) = o;
                }
            }
        }
        __syncthreads();
    }
}

// ---------------------------------------------------------------------------
extern "C" void kernel_launch(void* const* d_in, const int* in_sizes, int n_in,
                              void* d_out, int out_size) {
    const float* X  = (const float*)d_in[0];
    const int*   ra = (const int*)d_in[1];
    const int*   rb = (const int*)d_in[2];
    const int*   br = (const int*)d_in[3];
    const float* Wl = (const float*)d_in[4];
    const float* Wf = (const float*)d_in[5];
    const float* Wn = (const float*)d_in[6];
    const float* b  = (const float*)d_in[7];
    const float* bn = (const float*)d_in[8];
    float* out = (float*)d_out;

    const int n = in_sizes[0] / 128;   // 200000
    const int m = in_sizes[1];         // 2000000

    const int smem_x = (TILE_FLOATS + 2 * XC_FLOATS) * 4;      // 202752 B
    const int smem_f = (2 * TILE_FLOATS + 2 * FC_FLOATS) * 4;  // 202752 B

    static cudaStream_t s_side = nullptr;
    static cudaEvent_t ev_fork, ev_join;
    static bool init_done = false;
    if (!init_done) {
        cudaFuncSetAttribute(gemm_xwn_kernel,
                             cudaFuncAttributeMaxDynamicSharedMemorySize, smem_x);
        cudaFuncSetAttribute(gemm_final_kernel,
                             cudaFuncAttributeMaxDynamicSharedMemorySize, smem_f);
        cudaStreamCreateWithFlags(&s_side, cudaStreamNonBlocking);
        cudaEventCreateWithFlags(&ev_fork, cudaEventDisableTiming);
        cudaEventCreateWithFlags(&ev_join, cudaEventDisableTiming);
        init_done = true;
    }

    // Fork: edge counting sort runs on the side stream, concurrent with the
    // weight prep + xwn GEMM on the main (capture-origin) stream.
    cudaEventRecord(ev_fork, 0);
    cudaStreamWaitEvent(s_side, ev_fork, 0);

    hist_zero_kernel<<<(HPAD + 255) / 256, 256, 0, s_side>>>();
    hist_kernel<<<1024, 256, 0, s_side>>>(br, m);
    scan1_kernel<<<NBLK, 256, 0, s_side>>>();
    scan2_kernel<<<1, 256, 0, s_side>>>();
    scan3_kernel<<<(n + 256) / 256, 256, 0, s_side>>>(n, m);
    scatter_kernel<<<(m + 255) / 256, 256, 0, s_side>>>(ra, rb, br, m);
    cudaEventRecord(ev_join, s_side);

    prep_w_kernel<<<3, 256>>>(Wl, Wf, Wn);
    gemm_xwn_kernel<<<148, 256, smem_x>>>(X, n);

    // Join: conv needs both the sorted edges and the xwn projection.
    cudaStreamWaitEvent(0, ev_join, 0);
    conv_row_kernel<<<(n + 7) / 8, 256>>>(bn, n);
    gemm_final_kernel<<<148, 256, smem_f>>>(X, b, out, n);
}

// round 9
// speedup vs baseline: 1.0424x; 1.0424x over previous
#include <cuda_runtime.h>
#include <cuda_fp16.h>
#include <cstdint>
#include <cstddef>

// ---------------------------------------------------------------------------
// WL2 graph conv layer — tf32 mma.sync GEMMs (512 thr, 32-row warp tiles) +
// counting-sorted gather conv. Single stream (R7 skeleton).
//   prep_w -> edge sort -> gemm_xwn -> conv_row -> gemm_final
// ---------------------------------------------------------------------------

#define NMAX   200000
#define MEDGE  2000000
#define HPAD   200704              // 196 * 1024 (padded histogram length)
#define NBLK   196                 // scan blocks of 1024
#define MAXELEMS ((size_t)NMAX * 128)

__device__ __half g_xwnh[MAXELEMS];      // fp16 neighbor projection
__device__ float  g_conv[MAXELEMS];      // conv rows (written once, no atomics)
__device__ float  g_wt[3 * 128 * 128];   // W^T (K-major), tf32-rounded

__device__ int  g_hist[HPAD];
__device__ int  g_rowscan[HPAD];
__device__ int  g_bsum[NBLK];
__device__ int  g_bsumoff[NBLK];
__device__ int  g_rowstart[NMAX + 1];
__device__ int  g_cursor[NMAX];
__device__ int2 g_sab[MEDGE];            // sorted (ref_a, ref_b) pairs

// ---------------- helpers ----------------
__device__ __forceinline__ uint32_t f2tf32(float x) {
    uint32_t r;
    asm("cvt.rna.tf32.f32 %0, %1;" : "=r"(r) : "f"(x));
    return r;
}

__device__ __forceinline__ uint32_t smem_u32(const void* p) {
    uint32_t a;
    asm("{ .reg .u64 t; cvta.to.shared.u64 t, %1; cvt.u32.u64 %0, t; }"
        : "=r"(a) : "l"(p));
    return a;
}

__device__ __forceinline__ void cp_async16(uint32_t dst, const void* src) {
    asm volatile("cp.async.ca.shared.global [%0], [%1], 16;"
                 :: "r"(dst), "l"(src) : "memory");
}
__device__ __forceinline__ void cp_commit() {
    asm volatile("cp.async.commit_group;" ::: "memory");
}
__device__ __forceinline__ void cp_wait1() {
    asm volatile("cp.async.wait_group 1;" ::: "memory");
}

__device__ __forceinline__ void mma_tf32(float* c,
                                         uint32_t a0, uint32_t a1, uint32_t a2, uint32_t a3,
                                         uint32_t b0, uint32_t b1) {
    asm volatile(
        "mma.sync.aligned.m16n8k8.row.col.f32.tf32.tf32.f32 "
        "{%0,%1,%2,%3}, {%4,%5,%6,%7}, {%8,%9}, {%0,%1,%2,%3};"
        : "+f"(c[0]), "+f"(c[1]), "+f"(c[2]), "+f"(c[3])
        : "r"(a0), "r"(a1), "r"(a2), "r"(a3), "r"(b0), "r"(b1));
}

#define TPITCH 132
#define TILE_FLOATS (128 * TPITCH)

// ---------------------------------------------------------------------------
// Phase 0: W^T + tf32 rounding
// ---------------------------------------------------------------------------
__global__ void prep_w_kernel(const float* __restrict__ Wl,
                              const float* __restrict__ Wf,
                              const float* __restrict__ Wn) {
    const float* src = (blockIdx.x == 0) ? Wl : ((blockIdx.x == 1) ? Wf : Wn);
    float* dst = g_wt + blockIdx.x * 16384;
    for (int i = threadIdx.x; i < 16384; i += blockDim.x) {
        int n = i >> 7, k = i & 127;
        dst[i] = __uint_as_float(f2tf32(src[k * 128 + n]));
    }
}

// ---------------------------------------------------------------------------
// Phase 1: counting sort of edges by backref
// ---------------------------------------------------------------------------
__global__ void hist_zero_kernel() {
    int i = blockIdx.x * 256 + threadIdx.x;
    if (i < HPAD) g_hist[i] = 0;
}

__global__ void hist_kernel(const int* __restrict__ br, int m) {
    for (int e = blockIdx.x * 256 + threadIdx.x; e < m; e += gridDim.x * 256)
        atomicAdd(&g_hist[__ldg(br + e)], 1);
}

__global__ void scan1_kernel() {
    __shared__ int wsum[8];
    const int t = threadIdx.x;
    const int base = blockIdx.x * 1024 + t * 4;
    const int4 v = *reinterpret_cast<const int4*>(g_hist + base);
    const int s1 = v.x + v.y, s2 = s1 + v.z, s3 = s2 + v.w;
    const int lane = t & 31, w = t >> 5;
    int x = s3;
#pragma unroll
    for (int d = 1; d < 32; d <<= 1) {
        int y = __shfl_up_sync(0xffffffffu, x, d);
        if (lane >= d) x += y;
    }
    if (lane == 31) wsum[w] = x;
    __syncthreads();
    if (t < 8) {
        int v2 = wsum[t];
#pragma unroll
        for (int d = 1; d < 8; d <<= 1) {
            int y = __shfl_up_sync(0xffu, v2, d);
            if (t >= d) v2 += y;
        }
        wsum[t] = v2;
    }
    __syncthreads();
    const int woff = w ? wsum[w - 1] : 0;
    const int excl = woff + x - s3;
    int4 o;
    o.x = excl; o.y = excl + v.x; o.z = excl + s1; o.w = excl + s2;
    *reinterpret_cast<int4*>(g_rowscan + base) = o;
    if (t == 255) g_bsum[blockIdx.x] = wsum[7];
}

__global__ void scan2_kernel() {
    __shared__ int wsum[8];
    const int t = threadIdx.x;
    const int v = (t < NBLK) ? g_bsum[t] : 0;
    const int lane = t & 31, w = t >> 5;
    int x = v;
#pragma unroll
    for (int d = 1; d < 32; d <<= 1) {
        int y = __shfl_up_sync(0xffffffffu, x, d);
        if (lane >= d) x += y;
    }
    if (lane == 31) wsum[w] = x;
    __syncthreads();
    if (t < 8) {
        int v2 = wsum[t];
#pragma unroll
        for (int d = 1; d < 8; d <<= 1) {
            int y = __shfl_up_sync(0xffu, v2, d);
            if (t >= d) v2 += y;
        }
        wsum[t] = v2;
    }
    __syncthreads();
    const int woff = w ? wsum[w - 1] : 0;
    if (t < NBLK) g_bsumoff[t] = woff + x - v;
}

__global__ void scan3_kernel(int n, int m) {
    const int i = blockIdx.x * 256 + threadIdx.x;
    if (i < n) {
        const int val = g_rowscan[i] + g_bsumoff[i >> 10];
        g_rowstart[i] = val;
        g_cursor[i] = val;
    }
    if (i == 0) g_rowstart[n] = m;
}

__global__ void scatter_kernel(const int* __restrict__ ra,
                               const int* __restrict__ rb,
                               const int* __restrict__ br, int m) {
    const int e = blockIdx.x * 256 + threadIdx.x;
    if (e >= m) return;
    const int c = __ldg(br + e);
    const int p = atomicAdd(&g_cursor[c], 1);
    g_sab[p] = make_int2(__ldg(ra + e), __ldg(rb + e));
}

// ---------------------------------------------------------------------------
// B-tile loader (raw fp32, already tf32-rounded in g_wt) — 512 threads
// ---------------------------------------------------------------------------
__device__ __forceinline__ void load_b_tile(float* Bs, const float* __restrict__ Wt,
                                            int tid) {
    for (int i = tid; i < 4096; i += 512) {
        const int r = i >> 5, c4 = i & 31;
        float4 v = reinterpret_cast<const float4*>(Wt)[i];
        *reinterpret_cast<float4*>(&Bs[r * TPITCH + c4 * 4]) = v;
    }
}

// ---------------------------------------------------------------------------
// Phase 2: XW_n = X @ W_n, persistent, 512 threads, warp tile 32x32.
// 16 warps: m-group = wid&3 (32 rows), n-group = wid>>2 (32 cols, 4 nt).
// ---------------------------------------------------------------------------
#define XC_ROWS 128
#define XC_FLOATS (XC_ROWS * TPITCH)

__global__ __launch_bounds__(512, 1)
void gemm_xwn_kernel(const float* __restrict__ X, int nrows) {
    extern __shared__ __align__(16) float smem[];
    float* Bs = smem;
    float* Ab[2] = { smem + TILE_FLOATS, smem + TILE_FLOATS + XC_FLOATS };
    const uint32_t sb = smem_u32(smem);
    const uint32_t aoff[2] = { (uint32_t)(TILE_FLOATS * 4),
                               (uint32_t)((TILE_FLOATS + XC_FLOATS) * 4) };

    const int tid = threadIdx.x;
    const int ntiles = (nrows + XC_ROWS - 1) / XC_ROWS;
    const int stride = gridDim.x;

    load_b_tile(Bs, g_wt + 2 * 16384, tid);

    int tile0 = blockIdx.x;
    if (tile0 < ntiles) {
#pragma unroll
        for (int j = 0; j < 8; j++) {
            const int i = tid + j * 512;
            const int r = i >> 5, c4 = i & 31;
            const int gr = tile0 * XC_ROWS + r;
            if (gr < nrows)
                cp_async16(sb + aoff[0] + (uint32_t)(r * TPITCH + c4 * 4) * 4,
                           X + (size_t)gr * 128 + c4 * 4);
        }
    }
    cp_commit();

    const int wid = tid >> 5, lane = tid & 31;
    const int g = lane >> 2, t = lane & 3;
    const int m_base = (wid & 3) * 32;
    const int n_base = (wid >> 2) * 32;

    int buf = 0;
    for (int tile = tile0; tile < ntiles; tile += stride, buf ^= 1) {
        const int nxt = tile + stride;
        if (nxt < ntiles) {
#pragma unroll
            for (int j = 0; j < 8; j++) {
                const int i = tid + j * 512;
                const int r = i >> 5, c4 = i & 31;
                const int gr = nxt * XC_ROWS + r;
                if (gr < nrows)
                    cp_async16(sb + aoff[buf ^ 1] + (uint32_t)(r * TPITCH + c4 * 4) * 4,
                               X + (size_t)gr * 128 + c4 * 4);
            }
        }
        cp_commit();
        cp_wait1();
        __syncthreads();

        const float* As = Ab[buf];
        float acc[2][4][4];
#pragma unroll
        for (int h = 0; h < 2; h++)
#pragma unroll
            for (int nt = 0; nt < 4; nt++)
#pragma unroll
                for (int j = 0; j < 4; j++) acc[h][nt][j] = 0.f;

        const float* ar = &As[(m_base + g) * TPITCH + t];
        const float* br = &Bs[(n_base + g) * TPITCH + t];

#pragma unroll
        for (int ks = 0; ks < 16; ks++) {
            const int k = ks * 8;
            const uint32_t a0 = f2tf32(ar[k]);
            const uint32_t a1 = f2tf32(ar[8 * TPITCH + k]);
            const uint32_t a2 = f2tf32(ar[k + 4]);
            const uint32_t a3 = f2tf32(ar[8 * TPITCH + k + 4]);
            const uint32_t a4 = f2tf32(ar[16 * TPITCH + k]);
            const uint32_t a5 = f2tf32(ar[24 * TPITCH + k]);
            const uint32_t a6 = f2tf32(ar[16 * TPITCH + k + 4]);
            const uint32_t a7 = f2tf32(ar[24 * TPITCH + k + 4]);
#pragma unroll
            for (int nt = 0; nt < 4; nt++) {
                const uint32_t b0 = __float_as_uint(br[nt * 8 * TPITCH + k]);
                const uint32_t b1 = __float_as_uint(br[nt * 8 * TPITCH + k + 4]);
                mma_tf32(acc[0][nt], a0, a1, a2, a3, b0, b1);
                mma_tf32(acc[1][nt], a4, a5, a6, a7, b0, b1);
            }
        }

#pragma unroll
        for (int h = 0; h < 2; h++) {
            const int r0 = tile * XC_ROWS + m_base + h * 16 + g;
            const int r1 = r0 + 8;
#pragma unroll
            for (int nt = 0; nt < 4; nt++) {
                const int col = n_base + nt * 8 + 2 * t;
                if (r0 < nrows)
                    *reinterpret_cast<__half2*>(g_xwnh + (size_t)r0 * 128 + col) =
                        __floats2half2_rn(acc[h][nt][0], acc[h][nt][1]);
                if (r1 < nrows)
                    *reinterpret_cast<__half2*>(g_xwnh + (size_t)r1 * 128 + col) =
                        __floats2half2_rn(acc[h][nt][2], acc[h][nt][3]);
            }
        }
        __syncthreads();
    }
}

// ---------------------------------------------------------------------------
// Phase 3: conv rows. One warp per row; gather edges, relu, register sum,
// single coalesced store.
// ---------------------------------------------------------------------------
__global__ __launch_bounds__(256)
void conv_row_kernel(const float* __restrict__ bn, int n) {
    const int wid = threadIdx.x >> 5, lane = threadIdx.x & 31;
    const int r = blockIdx.x * 8 + wid;
    if (r >= n) return;

    const int s0 = g_rowstart[r];
    const int s1 = g_rowstart[r + 1];
    const float4 bb = __ldg(reinterpret_cast<const float4*>(bn) + lane);

    float ax = 0.f, ay = 0.f, az = 0.f, aw = 0.f;

    int i = s0;
    for (; i + 2 <= s1; i += 2) {
        const int2 e0 = __ldg(g_sab + i);
        const int2 e1 = __ldg(g_sab + i + 1);
        const uint2 pa0 = *reinterpret_cast<const uint2*>(g_xwnh + (size_t)e0.x * 128 + lane * 4);
        const uint2 pb0 = *reinterpret_cast<const uint2*>(g_xwnh + (size_t)e0.y * 128 + lane * 4);
        const uint2 pa1 = *reinterpret_cast<const uint2*>(g_xwnh + (size_t)e1.x * 128 + lane * 4);
        const uint2 pb1 = *reinterpret_cast<const uint2*>(g_xwnh + (size_t)e1.y * 128 + lane * 4);
        {
            const float2 x01 = __half22float2(*reinterpret_cast<const __half2*>(&pa0.x));
            const float2 x23 = __half22float2(*reinterpret_cast<const __half2*>(&pa0.y));
            const float2 y01 = __half22float2(*reinterpret_cast<const __half2*>(&pb0.x));
            const float2 y23 = __half22float2(*reinterpret_cast<const __half2*>(&pb0.y));
            ax += fmaxf(x01.x + y01.x + bb.x, 0.f);
            ay += fmaxf(x01.y + y01.y + bb.y, 0.f);
            az += fmaxf(x23.x + y23.x + bb.z, 0.f);
            aw += fmaxf(x23.y + y23.y + bb.w, 0.f);
        }
        {
            const float2 x01 = __half22float2(*reinterpret_cast<const __half2*>(&pa1.x));
            const float2 x23 = __half22float2(*reinterpret_cast<const __half2*>(&pa1.y));
            const float2 y01 = __half22float2(*reinterpret_cast<const __half2*>(&pb1.x));
            const float2 y23 = __half22float2(*reinterpret_cast<const __half2*>(&pb1.y));
            ax += fmaxf(x01.x + y01.x + bb.x, 0.f);
            ay += fmaxf(x01.y + y01.y + bb.y, 0.f);
            az += fmaxf(x23.x + y23.x + bb.z, 0.f);
            aw += fmaxf(x23.y + y23.y + bb.w, 0.f);
        }
    }
    if (i < s1) {
        const int2 e0 = __ldg(g_sab + i);
        const uint2 pa0 = *reinterpret_cast<const uint2*>(g_xwnh + (size_t)e0.x * 128 + lane * 4);
        const uint2 pb0 = *reinterpret_cast<const uint2*>(g_xwnh + (size_t)e0.y * 128 + lane * 4);
        const float2 x01 = __half22float2(*reinterpret_cast<const __half2*>(&pa0.x));
        const float2 x23 = __half22float2(*reinterpret_cast<const __half2*>(&pa0.y));
        const float2 y01 = __half22float2(*reinterpret_cast<const __half2*>(&pb0.x));
        const float2 y23 = __half22float2(*reinterpret_cast<const __half2*>(&pb0.y));
        ax += fmaxf(x01.x + y01.x + bb.x, 0.f);
        ay += fmaxf(x01.y + y01.y + bb.y, 0.f);
        az += fmaxf(x23.x + y23.x + bb.z, 0.f);
        aw += fmaxf(x23.y + y23.y + bb.w, 0.f);
    }

    *reinterpret_cast<float4*>(g_conv + (size_t)r * 128 + lane * 4) =
        make_float4(ax, ay, az, aw);
}

// ---------------------------------------------------------------------------
// Phase 4: fused final dual GEMM + epilogue. 512 threads, warp tile 32x16
// (dual accumulators), 64-row chunks. 16 warps: m = wid&1, n = wid>>1.
// ---------------------------------------------------------------------------
#define FC_ROWS 64
#define FC_FLOATS (FC_ROWS * TPITCH)

__global__ __launch_bounds__(512, 1)
void gemm_final_kernel(const float* __restrict__ X, const float* __restrict__ b,
                       float* __restrict__ out, int nrows) {
    extern __shared__ __align__(16) float smem[];
    float* Bsl = smem;
    float* Bsf = smem + TILE_FLOATS;
    float* Ab[2] = { smem + 2 * TILE_FLOATS, smem + 2 * TILE_FLOATS + FC_FLOATS };
    const uint32_t sb = smem_u32(smem);
    const uint32_t aoff[2] = { (uint32_t)(2 * TILE_FLOATS * 4),
                               (uint32_t)((2 * TILE_FLOATS + FC_FLOATS) * 4) };

    const int tid = threadIdx.x;
    const int ntiles = (nrows + FC_ROWS - 1) / FC_ROWS;
    const int stride = gridDim.x;

    load_b_tile(Bsl, g_wt + 0 * 16384, tid);
    load_b_tile(Bsf, g_wt + 1 * 16384, tid);

    int tile0 = blockIdx.x;
    if (tile0 < ntiles) {
#pragma unroll
        for (int j = 0; j < 4; j++) {
            const int i = tid + j * 512;
            const int r = i >> 5, c4 = i & 31;
            const int gr = tile0 * FC_ROWS + r;
            if (gr < nrows)
                cp_async16(sb + aoff[0] + (uint32_t)(r * TPITCH + c4 * 4) * 4,
                           X + (size_t)gr * 128 + c4 * 4);
        }
    }
    cp_commit();

    const int wid = tid >> 5, lane = tid & 31;
    const int g = lane >> 2, t = lane & 3;
    const int m_base = (wid & 1) * 32;
    const int n_base = (wid >> 1) * 16;

    int buf = 0;
    for (int tile = tile0; tile < ntiles; tile += stride, buf ^= 1) {
        const int nxt = tile + stride;
        if (nxt < ntiles) {
#pragma unroll
            for (int j = 0; j < 4; j++) {
                const int i = tid + j * 512;
                const int r = i >> 5, c4 = i & 31;
                const int gr = nxt * FC_ROWS + r;
                if (gr < nrows)
                    cp_async16(sb + aoff[buf ^ 1] + (uint32_t)(r * TPITCH + c4 * 4) * 4,
                               X + (size_t)gr * 128 + c4 * 4);
            }
        }
        cp_commit();
        cp_wait1();
        __syncthreads();

        const float* As = Ab[buf];
        float accl[2][2][4], accf[2][2][4];
#pragma unroll
        for (int h = 0; h < 2; h++)
#pragma unroll
            for (int nt = 0; nt < 2; nt++)
#pragma unroll
                for (int j = 0; j < 4; j++) { accl[h][nt][j] = 0.f; accf[h][nt][j] = 0.f; }

        const float* ar  = &As[(m_base + g) * TPITCH + t];
        const float* brl = &Bsl[(n_base + g) * TPITCH + t];
        const float* brf = &Bsf[(n_base + g) * TPITCH + t];

#pragma unroll
        for (int ks = 0; ks < 16; ks++) {
            const int k = ks * 8;
            const uint32_t a0 = f2tf32(ar[k]);
            const uint32_t a1 = f2tf32(ar[8 * TPITCH + k]);
            const uint32_t a2 = f2tf32(ar[k + 4]);
            const uint32_t a3 = f2tf32(ar[8 * TPITCH + k + 4]);
            const uint32_t a4 = f2tf32(ar[16 * TPITCH + k]);
            const uint32_t a5 = f2tf32(ar[24 * TPITCH + k]);
            const uint32_t a6 = f2tf32(ar[16 * TPITCH + k + 4]);
            const uint32_t a7 = f2tf32(ar[24 * TPITCH + k + 4]);
#pragma unroll
            for (int nt = 0; nt < 2; nt++) {
                const uint32_t bl0 = __float_as_uint(brl[nt * 8 * TPITCH + k]);
                const uint32_t bl1 = __float_as_uint(brl[nt * 8 * TPITCH + k + 4]);
                mma_tf32(accl[0][nt], a0, a1, a2, a3, bl0, bl1);
                mma_tf32(accl[1][nt], a4, a5, a6, a7, bl0, bl1);
                const uint32_t bf0 = __float_as_uint(brf[nt * 8 * TPITCH + k]);
                const uint32_t bf1 = __float_as_uint(brf[nt * 8 * TPITCH + k + 4]);
                mma_tf32(accf[0][nt], a0, a1, a2, a3, bf0, bf1);
                mma_tf32(accf[1][nt], a4, a5, a6, a7, bf0, bf1);
            }
        }

#pragma unroll
        for (int h = 0; h < 2; h++) {
            const int r0 = tile * FC_ROWS + m_base + h * 16 + g;
            const int r1 = r0 + 8;
#pragma unroll
            for (int nt = 0; nt < 2; nt++) {
                const int col = n_base + nt * 8 + 2 * t;
                const float2 b2 = __ldg(reinterpret_cast<const float2*>(b + col));
                if (r0 < nrows) {
                    const float2 cv = *reinterpret_cast<const float2*>(g_conv + (size_t)r0 * 128 + col);
                    float2 o;
                    o.x = fmaxf(fmaf(accf[h][nt][0], cv.x, accl[h][nt][0]) + b2.x, 0.f);
                    o.y = fmaxf(fmaf(accf[h][nt][1], cv.y, accl[h][nt][1]) + b2.y, 0.f);
                    *reinterpret_cast<float2*>(out + (size_t)r0 * 128 + col) = o;
                }
                if (r1 < nrows) {
                    const float2 cv = *reinterpret_cast<const float2*>(g_conv + (size_t)r1 * 128 + col);
                    float2 o;
                    o.x = fmaxf(fmaf(accf[h][nt][2], cv.x, accl[h][nt][2]) + b2.x, 0.f);
                    o.y = fmaxf(fmaf(accf[h][nt][3], cv.y, accl[h][nt][3]) + b2.y, 0.f);
                    *reinterpret_cast<float2*>(out + (size_t)r1 * 128 + col) = o;
                }
            }
        }
        __syncthreads();
    }
}

// ---------------------------------------------------------------------------
extern "C" void kernel_launch(void* const* d_in, const int* in_sizes, int n_in,
                              void* d_out, int out_size) {
    const float* X  = (const float*)d_in[0];
    const int*   ra = (const int*)d_in[1];
    const int*   rb = (const int*)d_in[2];
    const int*   br = (const int*)d_in[3];
    const float* Wl = (const float*)d_in[4];
    const float* Wf = (const float*)d_in[5];
    const float* Wn = (const float*)d_in[6];
    const float* b  = (const float*)d_in[7];
    const float* bn = (const float*)d_in[8];
    float* out = (float*)d_out;

    const int n = in_sizes[0] / 128;   // 200000
    const int m = in_sizes[1];         // 2000000

    const int smem_x = (TILE_FLOATS + 2 * XC_FLOATS) * 4;      // 202752 B
    const int smem_f = (2 * TILE_FLOATS + 2 * FC_FLOATS) * 4;  // 202752 B

    static bool attr_done = false;
    if (!attr_done) {
        cudaFuncSetAttribute(gemm_xwn_kernel,
                             cudaFuncAttributeMaxDynamicSharedMemorySize, smem_x);
        cudaFuncSetAttribute(gemm_final_kernel,
                             cudaFuncAttributeMaxDynamicSharedMemorySize, smem_f);
        attr_done = true;
    }

    prep_w_kernel<<<3, 256>>>(Wl, Wf, Wn);

    // Counting sort of edges by destination row
    hist_zero_kernel<<<(HPAD + 255) / 256, 256>>>();
    hist_kernel<<<1024, 256>>>(br, m);
    scan1_kernel<<<NBLK, 256>>>();
    scan2_kernel<<<1, 256>>>();
    scan3_kernel<<<(n + 256) / 256, 256>>>(n, m);
    scatter_kernel<<<(m + 255) / 256, 256>>>(ra, rb, br, m);

    gemm_xwn_kernel<<<148, 512, smem_x>>>(X, n);
    conv_row_kernel<<<(n + 7) / 8, 256>>>(bn, n);
    gemm_final_kernel<<<148, 512, smem_f>>>(X, b, out, n);
}

// round 10
// speedup vs baseline: 1.0958x; 1.0512x over previous
#include <cuda_runtime.h>
#include <cuda_fp16.h>
#include <cstdint>
#include <cstddef>

// ---------------------------------------------------------------------------
// WL2 graph conv layer — tf32 mma.sync GEMMs (R7 config) + counting-sorted
// gather conv (2 rows/warp). Launch order arranged so ncu (-s 5) profiles
// gemm_xwn.
//   prep_w -> hist_zero -> hist -> scan1 -> scan2 -> gemm_xwn
//   -> scan3 -> scatter -> conv_row -> gemm_final
// ---------------------------------------------------------------------------

#define NMAX   200000
#define MEDGE  2000000
#define HPAD   200704              // 196 * 1024 (padded histogram length)
#define NBLK   196                 // scan blocks of 1024
#define MAXELEMS ((size_t)NMAX * 128)

__device__ __half g_xwnh[MAXELEMS];      // fp16 neighbor projection
__device__ float  g_conv[MAXELEMS];      // conv rows (written once, no atomics)
__device__ float  g_wt[3 * 128 * 128];   // W^T (K-major), tf32-rounded

__device__ int  g_hist[HPAD];
__device__ int  g_rowscan[HPAD];
__device__ int  g_bsum[NBLK];
__device__ int  g_bsumoff[NBLK];
__device__ int  g_rowstart[NMAX + 1];
__device__ int  g_cursor[NMAX];
__device__ int2 g_sab[MEDGE];            // sorted (ref_a, ref_b) pairs

// ---------------- helpers ----------------
__device__ __forceinline__ uint32_t f2tf32(float x) {
    uint32_t r;
    asm("cvt.rna.tf32.f32 %0, %1;" : "=r"(r) : "f"(x));
    return r;
}

__device__ __forceinline__ uint32_t smem_u32(const void* p) {
    uint32_t a;
    asm("{ .reg .u64 t; cvta.to.shared.u64 t, %1; cvt.u32.u64 %0, t; }"
        : "=r"(a) : "l"(p));
    return a;
}

__device__ __forceinline__ void cp_async16(uint32_t dst, const void* src) {
    asm volatile("cp.async.ca.shared.global [%0], [%1], 16;"
                 :: "r"(dst), "l"(src) : "memory");
}
__device__ __forceinline__ void cp_commit() {
    asm volatile("cp.async.commit_group;" ::: "memory");
}
__device__ __forceinline__ void cp_wait1() {
    asm volatile("cp.async.wait_group 1;" ::: "memory");
}

__device__ __forceinline__ void mma_tf32(float* c,
                                         uint32_t a0, uint32_t a1, uint32_t a2, uint32_t a3,
                                         uint32_t b0, uint32_t b1) {
    asm volatile(
        "mma.sync.aligned.m16n8k8.row.col.f32.tf32.tf32.f32 "
        "{%0,%1,%2,%3}, {%4,%5,%6,%7}, {%8,%9}, {%0,%1,%2,%3};"
        : "+f"(c[0]), "+f"(c[1]), "+f"(c[2]), "+f"(c[3])
        : "r"(a0), "r"(a1), "r"(a2), "r"(a3), "r"(b0), "r"(b1));
}

#define TPITCH 132
#define TILE_FLOATS (128 * TPITCH)

// ---------------------------------------------------------------------------
// Phase 0: W^T + tf32 rounding
// ---------------------------------------------------------------------------
__global__ void prep_w_kernel(const float* __restrict__ Wl,
                              const float* __restrict__ Wf,
                              const float* __restrict__ Wn) {
    const float* src = (blockIdx.x == 0) ? Wl : ((blockIdx.x == 1) ? Wf : Wn);
    float* dst = g_wt + blockIdx.x * 16384;
    for (int i = threadIdx.x; i < 16384; i += blockDim.x) {
        int n = i >> 7, k = i & 127;
        dst[i] = __uint_as_float(f2tf32(src[k * 128 + n]));
    }
}

// ---------------------------------------------------------------------------
// Phase 1: counting sort of edges by backref
// ---------------------------------------------------------------------------
__global__ void hist_zero_kernel() {
    int i = blockIdx.x * 256 + threadIdx.x;
    if (i < HPAD) g_hist[i] = 0;
}

__global__ void hist_kernel(const int* __restrict__ br, int m) {
    for (int e = blockIdx.x * 256 + threadIdx.x; e < m; e += gridDim.x * 256)
        atomicAdd(&g_hist[__ldg(br + e)], 1);
}

__global__ void scan1_kernel() {
    __shared__ int wsum[8];
    const int t = threadIdx.x;
    const int base = blockIdx.x * 1024 + t * 4;
    const int4 v = *reinterpret_cast<const int4*>(g_hist + base);
    const int s1 = v.x + v.y, s2 = s1 + v.z, s3 = s2 + v.w;
    const int lane = t & 31, w = t >> 5;
    int x = s3;
#pragma unroll
    for (int d = 1; d < 32; d <<= 1) {
        int y = __shfl_up_sync(0xffffffffu, x, d);
        if (lane >= d) x += y;
    }
    if (lane == 31) wsum[w] = x;
    __syncthreads();
    if (t < 8) {
        int v2 = wsum[t];
#pragma unroll
        for (int d = 1; d < 8; d <<= 1) {
            int y = __shfl_up_sync(0xffu, v2, d);
            if (t >= d) v2 += y;
        }
        wsum[t] = v2;
    }
    __syncthreads();
    const int woff = w ? wsum[w - 1] : 0;
    const int excl = woff + x - s3;
    int4 o;
    o.x = excl; o.y = excl + v.x; o.z = excl + s1; o.w = excl + s2;
    *reinterpret_cast<int4*>(g_rowscan + base) = o;
    if (t == 255) g_bsum[blockIdx.x] = wsum[7];
}

__global__ void scan2_kernel() {
    __shared__ int wsum[8];
    const int t = threadIdx.x;
    const int v = (t < NBLK) ? g_bsum[t] : 0;
    const int lane = t & 31, w = t >> 5;
    int x = v;
#pragma unroll
    for (int d = 1; d < 32; d <<= 1) {
        int y = __shfl_up_sync(0xffffffffu, x, d);
        if (lane >= d) x += y;
    }
    if (lane == 31) wsum[w] = x;
    __syncthreads();
    if (t < 8) {
        int v2 = wsum[t];
#pragma unroll
        for (int d = 1; d < 8; d <<= 1) {
            int y = __shfl_up_sync(0xffu, v2, d);
            if (t >= d) v2 += y;
        }
        wsum[t] = v2;
    }
    __syncthreads();
    const int woff = w ? wsum[w - 1] : 0;
    if (t < NBLK) g_bsumoff[t] = woff + x - v;
}

__global__ void scan3_kernel(int n, int m) {
    const int i = blockIdx.x * 256 + threadIdx.x;
    if (i < n) {
        const int val = g_rowscan[i] + g_bsumoff[i >> 10];
        g_rowstart[i] = val;
        g_cursor[i] = val;
    }
    if (i == 0) g_rowstart[n] = m;
}

__global__ void scatter_kernel(const int* __restrict__ ra,
                               const int* __restrict__ rb,
                               const int* __restrict__ br, int m) {
    const int e = blockIdx.x * 256 + threadIdx.x;
    if (e >= m) return;
    const int c = __ldg(br + e);
    const int p = atomicAdd(&g_cursor[c], 1);
    g_sab[p] = make_int2(__ldg(ra + e), __ldg(rb + e));
}

// ---------------------------------------------------------------------------
// B-tile loader (raw fp32, already tf32-rounded in g_wt) — 512 threads
// ---------------------------------------------------------------------------
__device__ __forceinline__ void load_b_tile(float* Bs, const float* __restrict__ Wt,
                                            int tid) {
    for (int i = tid; i < 4096; i += 512) {
        const int r = i >> 5, c4 = i & 31;
        float4 v = reinterpret_cast<const float4*>(Wt)[i];
        *reinterpret_cast<float4*>(&Bs[r * TPITCH + c4 * 4]) = v;
    }
}

// ---------------------------------------------------------------------------
// Phase 2: XW_n = X @ W_n, persistent; 128-row chunks, double-buffered A.
// 16 warps: m-group = wid&7 (16 rows), n-group = wid>>3 (64 cols, 8 nt).
// (R7 configuration — empirically best.)
// ---------------------------------------------------------------------------
#define XC_ROWS 128
#define XC_FLOATS (XC_ROWS * TPITCH)

__global__ __launch_bounds__(512, 1)
void gemm_xwn_kernel(const float* __restrict__ X, int nrows) {
    extern __shared__ __align__(16) float smem[];
    float* Bs = smem;
    float* Ab[2] = { smem + TILE_FLOATS, smem + TILE_FLOATS + XC_FLOATS };
    const uint32_t sb = smem_u32(smem);
    const uint32_t aoff[2] = { (uint32_t)(TILE_FLOATS * 4),
                               (uint32_t)((TILE_FLOATS + XC_FLOATS) * 4) };

    const int tid = threadIdx.x;
    const int ntiles = (nrows + XC_ROWS - 1) / XC_ROWS;
    const int stride = gridDim.x;

    load_b_tile(Bs, g_wt + 2 * 16384, tid);

    int tile0 = blockIdx.x;
    if (tile0 < ntiles) {
#pragma unroll
        for (int j = 0; j < 8; j++) {
            const int i = tid + j * 512;
            const int r = i >> 5, c4 = i & 31;
            const int gr = tile0 * XC_ROWS + r;
            if (gr < nrows)
                cp_async16(sb + aoff[0] + (uint32_t)(r * TPITCH + c4 * 4) * 4,
                           X + (size_t)gr * 128 + c4 * 4);
        }
    }
    cp_commit();

    const int wid = tid >> 5, lane = tid & 31;
    const int g = lane >> 2, t = lane & 3;
    const int m_base = (wid & 7) * 16;
    const int n_base = (wid >> 3) * 64;

    int buf = 0;
    for (int tile = tile0; tile < ntiles; tile += stride, buf ^= 1) {
        const int nxt = tile + stride;
        if (nxt < ntiles) {
#pragma unroll
            for (int j = 0; j < 8; j++) {
                const int i = tid + j * 512;
                const int r = i >> 5, c4 = i & 31;
                const int gr = nxt * XC_ROWS + r;
                if (gr < nrows)
                    cp_async16(sb + aoff[buf ^ 1] + (uint32_t)(r * TPITCH + c4 * 4) * 4,
                               X + (size_t)gr * 128 + c4 * 4);
            }
        }
        cp_commit();
        cp_wait1();
        __syncthreads();

        const float* As = Ab[buf];
        float acc[8][4];
#pragma unroll
        for (int nt = 0; nt < 8; nt++)
#pragma unroll
            for (int j = 0; j < 4; j++) acc[nt][j] = 0.f;

        const float* ar0 = &As[(m_base + g) * TPITCH + t];
        const float* ar1 = &As[(m_base + 8 + g) * TPITCH + t];
        const float* br  = &Bs[(n_base + g) * TPITCH + t];

#pragma unroll
        for (int ks = 0; ks < 16; ks++) {
            const int k = ks * 8;
            const uint32_t a0 = f2tf32(ar0[k]);
            const uint32_t a1 = f2tf32(ar1[k]);
            const uint32_t a2 = f2tf32(ar0[k + 4]);
            const uint32_t a3 = f2tf32(ar1[k + 4]);
#pragma unroll
            for (int nt = 0; nt < 8; nt++) {
                const uint32_t b0 = __float_as_uint(br[nt * 8 * TPITCH + k]);
                const uint32_t b1 = __float_as_uint(br[nt * 8 * TPITCH + k + 4]);
                mma_tf32(acc[nt], a0, a1, a2, a3, b0, b1);
            }
        }

        const int r0 = tile * XC_ROWS + m_base + g;
        const int r1 = r0 + 8;
#pragma unroll
        for (int nt = 0; nt < 8; nt++) {
            const int col = n_base + nt * 8 + 2 * t;
            if (r0 < nrows)
                *reinterpret_cast<__half2*>(g_xwnh + (size_t)r0 * 128 + col) =
                    __floats2half2_rn(acc[nt][0], acc[nt][1]);
            if (r1 < nrows)
                *reinterpret_cast<__half2*>(g_xwnh + (size_t)r1 * 128 + col) =
                    __floats2half2_rn(acc[nt][2], acc[nt][3]);
        }
        __syncthreads();
    }
}

// ---------------------------------------------------------------------------
// Phase 3: conv rows. One warp per TWO rows (interleaved gathers for MLP);
// register sum, single coalesced store per row.
// ---------------------------------------------------------------------------
__global__ __launch_bounds__(256)
void conv_row_kernel(const float* __restrict__ bn, int n) {
    const int wid = threadIdx.x >> 5, lane = threadIdx.x & 31;
    const int r0 = (blockIdx.x * 8 + wid) * 2;
    if (r0 >= n) return;
    const int r1 = (r0 + 1 < n) ? (r0 + 1) : r0;   // degenerate tail: same row

    const int s0a = g_rowstart[r0];
    const int s0b = g_rowstart[r0 + 1];
    const int s1a = (r1 != r0) ? g_rowstart[r1] : s0a;
    const int s1b = (r1 != r0) ? g_rowstart[r1 + 1] : s0a;  // empty if degenerate

    const float4 bb = __ldg(reinterpret_cast<const float4*>(bn) + lane);

    float a0x = 0.f, a0y = 0.f, a0z = 0.f, a0w = 0.f;
    float a1x = 0.f, a1y = 0.f, a1z = 0.f, a1w = 0.f;

    int i0 = s0a, i1 = s1a;
    // Interleave both rows' edges: 2 edges (4 gathers) in flight per step.
    while (i0 < s0b && i1 < s1b) {
        const int2 e0 = __ldg(g_sab + i0);
        const int2 e1 = __ldg(g_sab + i1);
        const uint2 pa0 = *reinterpret_cast<const uint2*>(g_xwnh + (size_t)e0.x * 128 + lane * 4);
        const uint2 pb0 = *reinterpret_cast<const uint2*>(g_xwnh + (size_t)e0.y * 128 + lane * 4);
        const uint2 pa1 = *reinterpret_cast<const uint2*>(g_xwnh + (size_t)e1.x * 128 + lane * 4);
        const uint2 pb1 = *reinterpret_cast<const uint2*>(g_xwnh + (size_t)e1.y * 128 + lane * 4);
        {
            const float2 x01 = __half22float2(*reinterpret_cast<const __half2*>(&pa0.x));
            const float2 x23 = __half22float2(*reinterpret_cast<const __half2*>(&pa0.y));
            const float2 y01 = __half22float2(*reinterpret_cast<const __half2*>(&pb0.x));
            const float2 y23 = __half22float2(*reinterpret_cast<const __half2*>(&pb0.y));
            a0x += fmaxf(x01.x + y01.x + bb.x, 0.f);
            a0y += fmaxf(x01.y + y01.y + bb.y, 0.f);
            a0z += fmaxf(x23.x + y23.x + bb.z, 0.f);
            a0w += fmaxf(x23.y + y23.y + bb.w, 0.f);
        }
        {
            const float2 x01 = __half22float2(*reinterpret_cast<const __half2*>(&pa1.x));
            const float2 x23 = __half22float2(*reinterpret_cast<const __half2*>(&pa1.y));
            const float2 y01 = __half22float2(*reinterpret_cast<const __half2*>(&pb1.x));
            const float2 y23 = __half22float2(*reinterpret_cast<const __half2*>(&pb1.y));
            a1x += fmaxf(x01.x + y01.x + bb.x, 0.f);
            a1y += fmaxf(x01.y + y01.y + bb.y, 0.f);
            a1z += fmaxf(x23.x + y23.x + bb.z, 0.f);
            a1w += fmaxf(x23.y + y23.y + bb.w, 0.f);
        }
        i0++; i1++;
    }
    // Drain row 0 remainder (2-deep)
    for (; i0 + 2 <= s0b; i0 += 2) {
        const int2 e0 = __ldg(g_sab + i0);
        const int2 e1 = __ldg(g_sab + i0 + 1);
        const uint2 pa0 = *reinterpret_cast<const uint2*>(g_xwnh + (size_t)e0.x * 128 + lane * 4);
        const uint2 pb0 = *reinterpret_cast<const uint2*>(g_xwnh + (size_t)e0.y * 128 + lane * 4);
        const uint2 pa1 = *reinterpret_cast<const uint2*>(g_xwnh + (size_t)e1.x * 128 + lane * 4);
        const uint2 pb1 = *reinterpret_cast<const uint2*>(g_xwnh + (size_t)e1.y * 128 + lane * 4);
        {
            const float2 x01 = __half22float2(*reinterpret_cast<const __half2*>(&pa0.x));
            const float2 x23 = __half22float2(*reinterpret_cast<const __half2*>(&pa0.y));
            const float2 y01 = __half22float2(*reinterpret_cast<const __half2*>(&pb0.x));
            const float2 y23 = __half22float2(*reinterpret_cast<const __half2*>(&pb0.y));
            a0x += fmaxf(x01.x + y01.x + bb.x, 0.f);
            a0y += fmaxf(x01.y + y01.y + bb.y, 0.f);
            a0z += fmaxf(x23.x + y23.x + bb.z, 0.f);
            a0w += fmaxf(x23.y + y23.y + bb.w, 0.f);
        }
        {
            const float2 x01 = __half22float2(*reinterpret_cast<const __half2*>(&pa1.x));
            const float2 x23 = __half22float2(*reinterpret_cast<const __half2*>(&pa1.y));
            const float2 y01 = __half22float2(*reinterpret_cast<const __half2*>(&pb1.x));
            const float2 y23 = __half22float2(*reinterpret_cast<const __half2*>(&pb1.y));
            a0x += fmaxf(x01.x + y01.x + bb.x, 0.f);
            a0y += fmaxf(x01.y + y01.y + bb.y, 0.f);
            a0z += fmaxf(x23.x + y23.x + bb.z, 0.f);
            a0w += fmaxf(x23.y + y23.y + bb.w, 0.f);
        }
    }
    for (; i0 < s0b; i0++) {
        const int2 e0 = __ldg(g_sab + i0);
        const uint2 pa0 = *reinterpret_cast<const uint2*>(g_xwnh + (size_t)e0.x * 128 + lane * 4);
        const uint2 pb0 = *reinterpret_cast<const uint2*>(g_xwnh + (size_t)e0.y * 128 + lane * 4);
        const float2 x01 = __half22float2(*reinterpret_cast<const __half2*>(&pa0.x));
        const float2 x23 = __half22float2(*reinterpret_cast<const __half2*>(&pa0.y));
        const float2 y01 = __half22float2(*reinterpret_cast<const __half2*>(&pb0.x));
        const float2 y23 = __half22float2(*reinterpret_cast<const __half2*>(&pb0.y));
        a0x += fmaxf(x01.x + y01.x + bb.x, 0.f);
        a0y += fmaxf(x01.y + y01.y + bb.y, 0.f);
        a0z += fmaxf(x23.x + y23.x + bb.z, 0.f);
        a0w += fmaxf(x23.y + y23.y + bb.w, 0.f);
    }
    // Drain row 1 remainder (2-deep)
    for (; i1 + 2 <= s1b; i1 += 2) {
        const int2 e0 = __ldg(g_sab + i1);
        const int2 e1 = __ldg(g_sab + i1 + 1);
        const uint2 pa0 = *reinterpret_cast<const uint2*>(g_xwnh + (size_t)e0.x * 128 + lane * 4);
        const uint2 pb0 = *reinterpret_cast<const uint2*>(g_xwnh + (size_t)e0.y * 128 + lane * 4);
        const uint2 pa1 = *reinterpret_cast<const uint2*>(g_xwnh + (size_t)e1.x * 128 + lane * 4);
        const uint2 pb1 = *reinterpret_cast<const uint2*>(g_xwnh + (size_t)e1.y * 128 + lane * 4);
        {
            const float2 x01 = __half22float2(*reinterpret_cast<const __half2*>(&pa0.x));
            const float2 x23 = __half22float2(*reinterpret_cast<const __half2*>(&pa0.y));
            const float2 y01 = __half22float2(*reinterpret_cast<const __half2*>(&pb0.x));
            const float2 y23 = __half22float2(*reinterpret_cast<const __half2*>(&pb0.y));
            a1x += fmaxf(x01.x + y01.x + bb.x, 0.f);
            a1y += fmaxf(x01.y + y01.y + bb.y, 0.f);
            a1z += fmaxf(x23.x + y23.x + bb.z, 0.f);
            a1w += fmaxf(x23.y + y23.y + bb.w, 0.f);
        }
        {
            const float2 x01 = __half22float2(*reinterpret_cast<const __half2*>(&pa1.x));
            const float2 x23 = __half22float2(*reinterpret_cast<const __half2*>(&pa1.y));
            const float2 y01 = __half22float2(*reinterpret_cast<const __half2*>(&pb1.x));
            const float2 y23 = __half22float2(*reinterpret_cast<const __half2*>(&pb1.y));
            a1x += fmaxf(x01.x + y01.x + bb.x, 0.f);
            a1y += fmaxf(x01.y + y01.y + bb.y, 0.f);
            a1z += fmaxf(x23.x + y23.x + bb.z, 0.f);
            a1w += fmaxf(x23.y + y23.y + bb.w, 0.f);
        }
    }
    for (; i1 < s1b; i1++) {
        const int2 e0 = __ldg(g_sab + i1);
        const uint2 pa0 = *reinterpret_cast<const uint2*>(g_xwnh + (size_t)e0.x * 128 + lane * 4);
        const uint2 pb0 = *reinterpret_cast<const uint2*>(g_xwnh + (size_t)e0.y * 128 + lane * 4);
        const float2 x01 = __half22float2(*reinterpret_cast<const __half2*>(&pa0.x));
        const float2 x23 = __half22float2(*reinterpret_cast<const __half2*>(&pa0.y));
        const float2 y01 = __half22float2(*reinterpret_cast<const __half2*>(&pb0.x));
        const float2 y23 = __half22float2(*reinterpret_cast<const __half2*>(&pb0.y));
        a1x += fmaxf(x01.x + y01.x + bb.x, 0.f);
        a1y += fmaxf(x01.y + y01.y + bb.y, 0.f);
        a1z += fmaxf(x23.x + y23.x + bb.z, 0.f);
        a1w += fmaxf(x23.y + y23.y + bb.w, 0.f);
    }

    *reinterpret_cast<float4*>(g_conv + (size_t)r0 * 128 + lane * 4) =
        make_float4(a0x, a0y, a0z, a0w);
    if (r1 != r0)
        *reinterpret_cast<float4*>(g_conv + (size_t)r1 * 128 + lane * 4) =
            make_float4(a1x, a1y, a1z, a1w);
}

// ---------------------------------------------------------------------------
// Phase 4: persistent fused final: dual GEMM + epilogue, 64-row chunks.
// 16 warps: m-group = wid&3 (16 rows), n-group = wid>>2 (32 cols, 4 nt).
// (R7 configuration — empirically best.)
// ---------------------------------------------------------------------------
#define FC_ROWS 64
#define FC_FLOATS (FC_ROWS * TPITCH)

__global__ __launch_bounds__(512, 1)
void gemm_final_kernel(const float* __restrict__ X, const float* __restrict__ b,
                       float* __restrict__ out, int nrows) {
    extern __shared__ __align__(16) float smem[];
    float* Bsl = smem;
    float* Bsf = smem + TILE_FLOATS;
    float* Ab[2] = { smem + 2 * TILE_FLOATS, smem + 2 * TILE_FLOATS + FC_FLOATS };
    const uint32_t sb = smem_u32(smem);
    const uint32_t aoff[2] = { (uint32_t)(2 * TILE_FLOATS * 4),
                               (uint32_t)((2 * TILE_FLOATS + FC_FLOATS) * 4) };

    const int tid = threadIdx.x;
    const int ntiles = (nrows + FC_ROWS - 1) / FC_ROWS;
    const int stride = gridDim.x;

    load_b_tile(Bsl, g_wt + 0 * 16384, tid);
    load_b_tile(Bsf, g_wt + 1 * 16384, tid);

    int tile0 = blockIdx.x;
    if (tile0 < ntiles) {
#pragma unroll
        for (int j = 0; j < 4; j++) {
            const int i = tid + j * 512;
            const int r = i >> 5, c4 = i & 31;
            const int gr = tile0 * FC_ROWS + r;
            if (gr < nrows)
                cp_async16(sb + aoff[0] + (uint32_t)(r * TPITCH + c4 * 4) * 4,
                           X + (size_t)gr * 128 + c4 * 4);
        }
    }
    cp_commit();

    const int wid = tid >> 5, lane = tid & 31;
    const int g = lane >> 2, t = lane & 3;
    const int m_base = (wid & 3) * 16;
    const int n_base = (wid >> 2) * 32;

    int buf = 0;
    for (int tile = tile0; tile < ntiles; tile += stride, buf ^= 1) {
        const int nxt = tile + stride;
        if (nxt < ntiles) {
#pragma unroll
            for (int j = 0; j < 4; j++) {
                const int i = tid + j * 512;
                const int r = i >> 5, c4 = i & 31;
                const int gr = nxt * FC_ROWS + r;
                if (gr < nrows)
                    cp_async16(sb + aoff[buf ^ 1] + (uint32_t)(r * TPITCH + c4 * 4) * 4,
                               X + (size_t)gr * 128 + c4 * 4);
            }
        }
        cp_commit();
        cp_wait1();
        __syncthreads();

        const float* As = Ab[buf];
        float accl[4][4], accf[4][4];
#pragma unroll
        for (int nt = 0; nt < 4; nt++)
#pragma unroll
            for (int j = 0; j < 4; j++) { accl[nt][j] = 0.f; accf[nt][j] = 0.f; }

        const float* ar0 = &As[(m_base + g) * TPITCH + t];
        const float* ar1 = &As[(m_base + 8 + g) * TPITCH + t];
        const float* brl = &Bsl[(n_base + g) * TPITCH + t];
        const float* brf = &Bsf[(n_base + g) * TPITCH + t];

#pragma unroll
        for (int ks = 0; ks < 16; ks++) {
            const int k = ks * 8;
            const uint32_t a0 = f2tf32(ar0[k]);
            const uint32_t a1 = f2tf32(ar1[k]);
            const uint32_t a2 = f2tf32(ar0[k + 4]);
            const uint32_t a3 = f2tf32(ar1[k + 4]);
#pragma unroll
            for (int nt = 0; nt < 4; nt++) {
                const uint32_t bl0 = __float_as_uint(brl[nt * 8 * TPITCH + k]);
                const uint32_t bl1 = __float_as_uint(brl[nt * 8 * TPITCH + k + 4]);
                mma_tf32(accl[nt], a0, a1, a2, a3, bl0, bl1);
                const uint32_t bf0 = __float_as_uint(brf[nt * 8 * TPITCH + k]);
                const uint32_t bf1 = __float_as_uint(brf[nt * 8 * TPITCH + k + 4]);
                mma_tf32(accf[nt], a0, a1, a2, a3, bf0, bf1);
            }
        }

        const int r0 = tile * FC_ROWS + m_base + g;
        const int r1 = r0 + 8;
#pragma unroll
        for (int nt = 0; nt < 4; nt++) {
            const int col = n_base + nt * 8 + 2 * t;
            const float2 b2 = __ldg(reinterpret_cast<const float2*>(b + col));
            if (r0 < nrows) {
                const float2 cv = *reinterpret_cast<const float2*>(g_conv + (size_t)r0 * 128 + col);
                float2 o;
                o.x = fmaxf(fmaf(accf[nt][0], cv.x, accl[nt][0]) + b2.x, 0.f);
                o.y = fmaxf(fmaf(accf[nt][1], cv.y, accl[nt][1]) + b2.y, 0.f);
                *reinterpret_cast<float2*>(out + (size_t)r0 * 128 + col) = o;
            }
            if (r1 < nrows) {
                const float2 cv = *reinterpret_cast<const float2*>(g_conv + (size_t)r1 * 128 + col);
                float2 o;
                o.x = fmaxf(fmaf(accf[nt][2], cv.x, accl[nt][2]) + b2.x, 0.f);
                o.y = fmaxf(fmaf(accf[nt][3], cv.y, accl[nt][3]) + b2.y, 0.f);
                *reinterpret_cast<float2*>(out + (size_t)r1 * 128 + col) = o;
            }
        }
        __syncthreads();
    }
}

// ---------------------------------------------------------------------------
extern "C" void kernel_launch(void* const* d_in, const int* in_sizes, int n_in,
                              void* d_out, int out_size) {
    const float* X  = (const float*)d_in[0];
    const int*   ra = (const int*)d_in[1];
    const int*   rb = (const int*)d_in[2];
    const int*   br = (const int*)d_in[3];
    const float* Wl = (const float*)d_in[4];
    const float* Wf = (const float*)d_in[5];
    const float* Wn = (const float*)d_in[6];
    const float* b  = (const float*)d_in[7];
    const float* bn = (const float*)d_in[8];
    float* out = (float*)d_out;

    const int n = in_sizes[0] / 128;   // 200000
    const int m = in_sizes[1];         // 2000000

    const int smem_x = (TILE_FLOATS + 2 * XC_FLOATS) * 4;      // 202752 B
    const int smem_f = (2 * TILE_FLOATS + 2 * FC_FLOATS) * 4;  // 202752 B

    static bool attr_done = false;
    if (!attr_done) {
        cudaFuncSetAttribute(gemm_xwn_kernel,
                             cudaFuncAttributeMaxDynamicSharedMemorySize, smem_x);
        cudaFuncSetAttribute(gemm_final_kernel,
                             cudaFuncAttributeMaxDynamicSharedMemorySize, smem_f);
        attr_done = true;
    }

    // Launch order: gemm_xwn is the 6th launch so ncu (-s 5 -c 1) profiles it.
    prep_w_kernel<<<3, 256>>>(Wl, Wf, Wn);                    // 1
    hist_zero_kernel<<<(HPAD + 255) / 256, 256>>>();          // 2
    hist_kernel<<<1024, 256>>>(br, m);                        // 3
    scan1_kernel<<<NBLK, 256>>>();                            // 4
    scan2_kernel<<<1, 256>>>();                               // 5
    gemm_xwn_kernel<<<148, 512, smem_x>>>(X, n);              // 6  <- profiled
    scan3_kernel<<<(n + 256) / 256, 256>>>(n, m);             // 7
    scatter_kernel<<<(m + 255) / 256, 256>>>(ra, rb, br, m);  // 8
    conv_row_kernel<<<(n + 15) / 16, 256>>>(bn, n);           // 9
    gemm_final_kernel<<<148, 512, smem_f>>>(X, b, out, n);    // 10
}

// round 13
// speedup vs baseline: 1.3555x; 1.2370x over previous
#include <cuda_runtime.h>
#include <cuda_fp16.h>
#include <cstdint>
#include <cstddef>

// ---------------------------------------------------------------------------
// WL2 graph conv layer — fp16 mma.sync (m16n8k16, fp32 accum) GEMMs +
// counting-sorted gather conv (2 rows/warp).
//   prep_w(fp16 W^T) -> prep_x(fp16 X) -> edge sort -> gemm_xwn ->
//   conv_row -> gemm_final
// R13: fixes R12's gemm_final tile coverage bug (64-col hole) by restoring
// the proven 64-row-chunk / 4x4 n-group geometry, ported to fp16.
// ---------------------------------------------------------------------------

#define NMAX   200000
#define MEDGE  2000000
#define HPAD   200704              // 196 * 1024 (padded histogram length)
#define NBLK   196                 // scan blocks of 1024
#define MAXELEMS ((size_t)NMAX * 128)

__device__ __half g_xh[MAXELEMS];        // fp16 copy of X
__device__ __half g_xwnh[MAXELEMS];      // fp16 neighbor projection
__device__ float  g_conv[MAXELEMS];      // conv rows (written once, no atomics)
__device__ __half g_wth[3 * 128 * 128];  // W^T (K-major), fp16

__device__ int  g_hist[HPAD];
__device__ int  g_rowscan[HPAD];
__device__ int  g_bsum[NBLK];
__device__ int  g_bsumoff[NBLK];
__device__ int  g_rowstart[NMAX + 1];
__device__ int  g_cursor[NMAX];
__device__ int2 g_sab[MEDGE];            // sorted (ref_a, ref_b) pairs

// ---------------- helpers ----------------
__device__ __forceinline__ uint32_t smem_u32(const void* p) {
    uint32_t a;
    asm("{ .reg .u64 t; cvta.to.shared.u64 t, %1; cvt.u32.u64 %0, t; }"
        : "=r"(a) : "l"(p));
    return a;
}

__device__ __forceinline__ void cp_async16(uint32_t dst, const void* src) {
    asm volatile("cp.async.ca.shared.global [%0], [%1], 16;"
                 :: "r"(dst), "l"(src) : "memory");
}
__device__ __forceinline__ void cp_commit() {
    asm volatile("cp.async.commit_group;" ::: "memory");
}
__device__ __forceinline__ void cp_wait1() {
    asm volatile("cp.async.wait_group 1;" ::: "memory");
}

// fp16 mma with fp32 accumulators: D = A(16x16,row) * B(16x8,col) + D
__device__ __forceinline__ void mma_f16(float* c,
                                        uint32_t a0, uint32_t a1, uint32_t a2, uint32_t a3,
                                        uint32_t b0, uint32_t b1) {
    asm volatile(
        "mma.sync.aligned.m16n8k16.row.col.f32.f16.f16.f32 "
        "{%0,%1,%2,%3}, {%4,%5,%6,%7}, {%8,%9}, {%0,%1,%2,%3};"
        : "+f"(c[0]), "+f"(c[1]), "+f"(c[2]), "+f"(c[3])
        : "r"(a0), "r"(a1), "r"(a2), "r"(a3), "r"(b0), "r"(b1));
}

// smem tile geometry: rows of 128 halves padded to 136 (272 B, 16B-aligned,
// 68 words == 4 mod 32 -> all fragment loads bank-conflict-free).
#define HPITCH_B    272                   // bytes per padded row
#define TILE_BYTES  (128 * HPITCH_B)      // 34816 B per 128-row tile
#define FTILE_BYTES (64 * HPITCH_B)       // 17408 B per 64-row A tile

// ---------------------------------------------------------------------------
// Phase 0a: W^T -> fp16
// ---------------------------------------------------------------------------
__global__ void prep_w_kernel(const float* __restrict__ Wl,
                              const float* __restrict__ Wf,
                              const float* __restrict__ Wn) {
    const float* src = (blockIdx.x == 0) ? Wl : ((blockIdx.x == 1) ? Wf : Wn);
    __half* dst = g_wth + blockIdx.x * 16384;
    for (int i = threadIdx.x; i < 16384; i += blockDim.x) {
        int n = i >> 7, k = i & 127;
        dst[i] = __float2half_rn(src[k * 128 + n]);   // [n][k]
    }
}

// ---------------------------------------------------------------------------
// Phase 0b: X -> fp16
// ---------------------------------------------------------------------------
__global__ void prep_x_kernel(const float* __restrict__ X, int total4) {
    const int i = blockIdx.x * 256 + threadIdx.x;
    if (i >= total4) return;
    const float4 v = reinterpret_cast<const float4*>(X)[i];
    const __half2 h0 = __floats2half2_rn(v.x, v.y);
    const __half2 h1 = __floats2half2_rn(v.z, v.w);
    uint2 o;
    o.x = *reinterpret_cast<const uint32_t*>(&h0);
    o.y = *reinterpret_cast<const uint32_t*>(&h1);
    reinterpret_cast<uint2*>(g_xh)[i] = o;
}

// ---------------------------------------------------------------------------
// Phase 1: counting sort of edges by backref
// ---------------------------------------------------------------------------
__global__ void hist_zero_kernel() {
    int i = blockIdx.x * 256 + threadIdx.x;
    if (i < HPAD) g_hist[i] = 0;
}

__global__ void hist_kernel(const int* __restrict__ br, int m) {
    for (int e = blockIdx.x * 256 + threadIdx.x; e < m; e += gridDim.x * 256)
        atomicAdd(&g_hist[__ldg(br + e)], 1);
}

__global__ void scan1_kernel() {
    __shared__ int wsum[8];
    const int t = threadIdx.x;
    const int base = blockIdx.x * 1024 + t * 4;
    const int4 v = *reinterpret_cast<const int4*>(g_hist + base);
    const int s1 = v.x + v.y, s2 = s1 + v.z, s3 = s2 + v.w;
    const int lane = t & 31, w = t >> 5;
    int x = s3;
#pragma unroll
    for (int d = 1; d < 32; d <<= 1) {
        int y = __shfl_up_sync(0xffffffffu, x, d);
        if (lane >= d) x += y;
    }
    if (lane == 31) wsum[w] = x;
    __syncthreads();
    if (t < 8) {
        int v2 = wsum[t];
#pragma unroll
        for (int d = 1; d < 8; d <<= 1) {
            int y = __shfl_up_sync(0xffu, v2, d);
            if (t >= d) v2 += y;
        }
        wsum[t] = v2;
    }
    __syncthreads();
    const int woff = w ? wsum[w - 1] : 0;
    const int excl = woff + x - s3;
    int4 o;
    o.x = excl; o.y = excl + v.x; o.z = excl + s1; o.w = excl + s2;
    *reinterpret_cast<int4*>(g_rowscan + base) = o;
    if (t == 255) g_bsum[blockIdx.x] = wsum[7];
}

__global__ void scan2_kernel() {
    __shared__ int wsum[8];
    const int t = threadIdx.x;
    const int v = (t < NBLK) ? g_bsum[t] : 0;
    const int lane = t & 31, w = t >> 5;
    int x = v;
#pragma unroll
    for (int d = 1; d < 32; d <<= 1) {
        int y = __shfl_up_sync(0xffffffffu, x, d);
        if (lane >= d) x += y;
    }
    if (lane == 31) wsum[w] = x;
    __syncthreads();
    if (t < 8) {
        int v2 = wsum[t];
#pragma unroll
        for (int d = 1; d < 8; d <<= 1) {
            int y = __shfl_up_sync(0xffu, v2, d);
            if (t >= d) v2 += y;
        }
        wsum[t] = v2;
    }
    __syncthreads();
    const int woff = w ? wsum[w - 1] : 0;
    if (t < NBLK) g_bsumoff[t] = woff + x - v;
}

__global__ void scan3_kernel(int n, int m) {
    const int i = blockIdx.x * 256 + threadIdx.x;
    if (i < n) {
        const int val = g_rowscan[i] + g_bsumoff[i >> 10];
        g_rowstart[i] = val;
        g_cursor[i] = val;
    }
    if (i == 0) g_rowstart[n] = m;
}

__global__ void scatter_kernel(const int* __restrict__ ra,
                               const int* __restrict__ rb,
                               const int* __restrict__ br, int m) {
    const int e = blockIdx.x * 256 + threadIdx.x;
    if (e >= m) return;
    const int c = __ldg(br + e);
    const int p = atomicAdd(&g_cursor[c], 1);
    g_sab[p] = make_int2(__ldg(ra + e), __ldg(rb + e));
}

// ---------------------------------------------------------------------------
// B-tile loader: g_wth [n][k] fp16 -> smem padded rows. 512 threads.
// ---------------------------------------------------------------------------
__device__ __forceinline__ void load_b_tile(char* dst, const __half* __restrict__ Wt,
                                            int tid) {
    for (int i = tid; i < 2048; i += 512) {
        const int r = i >> 4, c = i & 15;
        const uint4 v = *reinterpret_cast<const uint4*>(Wt + r * 128 + c * 8);
        *reinterpret_cast<uint4*>(dst + r * HPITCH_B + c * 16) = v;
    }
}

// ---------------------------------------------------------------------------
// Phase 2: XW_n = X @ W_n, persistent; 128-row chunks, double-buffered A.
// 16 warps: m-group = wid&7 (16 rows), n-group = wid>>3 (64 cols, 8 nt).
// Full 128x128 tile coverage: 8x16 rows, 2x64 cols.
// ---------------------------------------------------------------------------
#define XB_OFF   0
#define XA0_OFF  TILE_BYTES
#define XA1_OFF  (2 * TILE_BYTES)
#define SMEM_X   (3 * TILE_BYTES)      // 104448 B

__global__ __launch_bounds__(512, 1)
void gemm_xwn_kernel(int nrows) {
    extern __shared__ __align__(16) char smem[];
    const uint32_t sb = smem_u32(smem);

    const int tid = threadIdx.x;
    const int ntiles = (nrows + 127) / 128;
    const int stride = gridDim.x;
    const uint32_t aoff[2] = { XA0_OFF, XA1_OFF };

    load_b_tile(smem + XB_OFF, g_wth + 2 * 16384, tid);

    int tile0 = blockIdx.x;
    if (tile0 < ntiles) {
#pragma unroll
        for (int j = 0; j < 4; j++) {
            const int i = tid + j * 512;
            const int r = i >> 4, c = i & 15;
            const int gr = tile0 * 128 + r;
            if (gr < nrows)
                cp_async16(sb + aoff[0] + (uint32_t)(r * HPITCH_B + c * 16),
                           g_xh + (size_t)gr * 128 + c * 8);
        }
    }
    cp_commit();

    const int wid = tid >> 5, lane = tid & 31;
    const int g = lane >> 2, t = lane & 3;
    const int m_base = (wid & 7) * 16;
    const int n_base = (wid >> 3) * 64;

    int buf = 0;
    for (int tile = tile0; tile < ntiles; tile += stride, buf ^= 1) {
        const int nxt = tile + stride;
        if (nxt < ntiles) {
#pragma unroll
            for (int j = 0; j < 4; j++) {
                const int i = tid + j * 512;
                const int r = i >> 4, c = i & 15;
                const int gr = nxt * 128 + r;
                if (gr < nrows)
                    cp_async16(sb + aoff[buf ^ 1] + (uint32_t)(r * HPITCH_B + c * 16),
                               g_xh + (size_t)gr * 128 + c * 8);
            }
        }
        cp_commit();
        cp_wait1();
        __syncthreads();

        float acc[8][4];
#pragma unroll
        for (int nt = 0; nt < 8; nt++)
#pragma unroll
            for (int j = 0; j < 4; j++) acc[nt][j] = 0.f;

        const char* ar = smem + aoff[buf] + (m_base + g) * HPITCH_B + 4 * t;
        const char* br = smem + XB_OFF + (n_base + g) * HPITCH_B + 4 * t;

#pragma unroll
        for (int ks = 0; ks < 8; ks++) {
            const int kb = ks * 32;   // 16 halves = 32 bytes per K-step
            const uint32_t a0 = *reinterpret_cast<const uint32_t*>(ar + kb);
            const uint32_t a1 = *reinterpret_cast<const uint32_t*>(ar + 8 * HPITCH_B + kb);
            const uint32_t a2 = *reinterpret_cast<const uint32_t*>(ar + kb + 16);
            const uint32_t a3 = *reinterpret_cast<const uint32_t*>(ar + 8 * HPITCH_B + kb + 16);
#pragma unroll
            for (int nt = 0; nt < 8; nt++) {
                const uint32_t b0 = *reinterpret_cast<const uint32_t*>(br + nt * 8 * HPITCH_B + kb);
                const uint32_t b1 = *reinterpret_cast<const uint32_t*>(br + nt * 8 * HPITCH_B + kb + 16);
                mma_f16(acc[nt], a0, a1, a2, a3, b0, b1);
            }
        }

        const int r0 = tile * 128 + m_base + g;
        const int r1 = r0 + 8;
#pragma unroll
        for (int nt = 0; nt < 8; nt++) {
            const int col = n_base + nt * 8 + 2 * t;
            if (r0 < nrows)
                *reinterpret_cast<__half2*>(g_xwnh + (size_t)r0 * 128 + col) =
                    __floats2half2_rn(acc[nt][0], acc[nt][1]);
            if (r1 < nrows)
                *reinterpret_cast<__half2*>(g_xwnh + (size_t)r1 * 128 + col) =
                    __floats2half2_rn(acc[nt][2], acc[nt][3]);
        }
        __syncthreads();
    }
}

// ---------------------------------------------------------------------------
// Phase 3: conv rows. One warp per TWO rows (interleaved gathers for MLP);
// register sum, single coalesced store per row.
// ---------------------------------------------------------------------------
__global__ __launch_bounds__(256)
void conv_row_kernel(const float* __restrict__ bn, int n) {
    const int wid = threadIdx.x >> 5, lane = threadIdx.x & 31;
    const int r0 = (blockIdx.x * 8 + wid) * 2;
    if (r0 >= n) return;
    const int r1 = (r0 + 1 < n) ? (r0 + 1) : r0;

    const int s0a = g_rowstart[r0];
    const int s0b = g_rowstart[r0 + 1];
    const int s1a = (r1 != r0) ? g_rowstart[r1] : s0a;
    const int s1b = (r1 != r0) ? g_rowstart[r1 + 1] : s0a;

    const float4 bb = __ldg(reinterpret_cast<const float4*>(bn) + lane);

    float a0x = 0.f, a0y = 0.f, a0z = 0.f, a0w = 0.f;
    float a1x = 0.f, a1y = 0.f, a1z = 0.f, a1w = 0.f;

    int i0 = s0a, i1 = s1a;
    while (i0 < s0b && i1 < s1b) {
        const int2 e0 = __ldg(g_sab + i0);
        const int2 e1 = __ldg(g_sab + i1);
        const uint2 pa0 = *reinterpret_cast<const uint2*>(g_xwnh + (size_t)e0.x * 128 + lane * 4);
        const uint2 pb0 = *reinterpret_cast<const uint2*>(g_xwnh + (size_t)e0.y * 128 + lane * 4);
        const uint2 pa1 = *reinterpret_cast<const uint2*>(g_xwnh + (size_t)e1.x * 128 + lane * 4);
        const uint2 pb1 = *reinterpret_cast<const uint2*>(g_xwnh + (size_t)e1.y * 128 + lane * 4);
        {
            const float2 x01 = __half22float2(*reinterpret_cast<const __half2*>(&pa0.x));
            const float2 x23 = __half22float2(*reinterpret_cast<const __half2*>(&pa0.y));
            const float2 y01 = __half22float2(*reinterpret_cast<const __half2*>(&pb0.x));
            const float2 y23 = __half22float2(*reinterpret_cast<const __half2*>(&pb0.y));
            a0x += fmaxf(x01.x + y01.x + bb.x, 0.f);
            a0y += fmaxf(x01.y + y01.y + bb.y, 0.f);
            a0z += fmaxf(x23.x + y23.x + bb.z, 0.f);
            a0w += fmaxf(x23.y + y23.y + bb.w, 0.f);
        }
        {
            const float2 x01 = __half22float2(*reinterpret_cast<const __half2*>(&pa1.x));
            const float2 x23 = __half22float2(*reinterpret_cast<const __half2*>(&pa1.y));
            const float2 y01 = __half22float2(*reinterpret_cast<const __half2*>(&pb1.x));
            const float2 y23 = __half22float2(*reinterpret_cast<const __half2*>(&pb1.y));
            a1x += fmaxf(x01.x + y01.x + bb.x, 0.f);
            a1y += fmaxf(x01.y + y01.y + bb.y, 0.f);
            a1z += fmaxf(x23.x + y23.x + bb.z, 0.f);
            a1w += fmaxf(x23.y + y23.y + bb.w, 0.f);
        }
        i0++; i1++;
    }
    for (; i0 + 2 <= s0b; i0 += 2) {
        const int2 e0 = __ldg(g_sab + i0);
        const int2 e1 = __ldg(g_sab + i0 + 1);
        const uint2 pa0 = *reinterpret_cast<const uint2*>(g_xwnh + (size_t)e0.x * 128 + lane * 4);
        const uint2 pb0 = *reinterpret_cast<const uint2*>(g_xwnh + (size_t)e0.y * 128 + lane * 4);
        const uint2 pa1 = *reinterpret_cast<const uint2*>(g_xwnh + (size_t)e1.x * 128 + lane * 4);
        const uint2 pb1 = *reinterpret_cast<const uint2*>(g_xwnh + (size_t)e1.y * 128 + lane * 4);
        {
            const float2 x01 = __half22float2(*reinterpret_cast<const __half2*>(&pa0.x));
            const float2 x23 = __half22float2(*reinterpret_cast<const __half2*>(&pa0.y));
            const float2 y01 = __half22float2(*reinterpret_cast<const __half2*>(&pb0.x));
            const float2 y23 = __half22float2(*reinterpret_cast<const __half2*>(&pb0.y));
            a0x += fmaxf(x01.x + y01.x + bb.x, 0.f);
            a0y += fmaxf(x01.y + y01.y + bb.y, 0.f);
            a0z += fmaxf(x23.x + y23.x + bb.z, 0.f);
            a0w += fmaxf(x23.y + y23.y + bb.w, 0.f);
        }
        {
            const float2 x01 = __half22float2(*reinterpret_cast<const __half2*>(&pa1.x));
            const float2 x23 = __half22float2(*reinterpret_cast<const __half2*>(&pa1.y));
            const float2 y01 = __half22float2(*reinterpret_cast<const __half2*>(&pb1.x));
            const float2 y23 = __half22float2(*reinterpret_cast<const __half2*>(&pb1.y));
            a0x += fmaxf(x01.x + y01.x + bb.x, 0.f);
            a0y += fmaxf(x01.y + y01.y + bb.y, 0.f);
            a0z += fmaxf(x23.x + y23.x + bb.z, 0.f);
            a0w += fmaxf(x23.y + y23.y + bb.w, 0.f);
        }
    }
    for (; i0 < s0b; i0++) {
        const int2 e0 = __ldg(g_sab + i0);
        const uint2 pa0 = *reinterpret_cast<const uint2*>(g_xwnh + (size_t)e0.x * 128 + lane * 4);
        const uint2 pb0 = *reinterpret_cast<const uint2*>(g_xwnh + (size_t)e0.y * 128 + lane * 4);
        const float2 x01 = __half22float2(*reinterpret_cast<const __half2*>(&pa0.x));
        const float2 x23 = __half22float2(*reinterpret_cast<const __half2*>(&pa0.y));
        const float2 y01 = __half22float2(*reinterpret_cast<const __half2*>(&pb0.x));
        const float2 y23 = __half22float2(*reinterpret_cast<const __half2*>(&pb0.y));
        a0x += fmaxf(x01.x + y01.x + bb.x, 0.f);
        a0y += fmaxf(x01.y + y01.y + bb.y, 0.f);
        a0z += fmaxf(x23.x + y23.x + bb.z, 0.f);
        a0w += fmaxf(x23.y + y23.y + bb.w, 0.f);
    }
    for (; i1 + 2 <= s1b; i1 += 2) {
        const int2 e0 = __ldg(g_sab + i1);
        const int2 e1 = __ldg(g_sab + i1 + 1);
        const uint2 pa0 = *reinterpret_cast<const uint2*>(g_xwnh + (size_t)e0.x * 128 + lane * 4);
        const uint2 pb0 = *reinterpret_cast<const uint2*>(g_xwnh + (size_t)e0.y * 128 + lane * 4);
        const uint2 pa1 = *reinterpret_cast<const uint2*>(g_xwnh + (size_t)e1.x * 128 + lane * 4);
        const uint2 pb1 = *reinterpret_cast<const uint2*>(g_xwnh + (size_t)e1.y * 128 + lane * 4);
        {
            const float2 x01 = __half22float2(*reinterpret_cast<const __half2*>(&pa0.x));
            const float2 x23 = __half22float2(*reinterpret_cast<const __half2*>(&pa0.y));
            const float2 y01 = __half22float2(*reinterpret_cast<const __half2*>(&pb0.x));
            const float2 y23 = __half22float2(*reinterpret_cast<const __half2*>(&pb0.y));
            a1x += fmaxf(x01.x + y01.x + bb.x, 0.f);
            a1y += fmaxf(x01.y + y01.y + bb.y, 0.f);
            a1z += fmaxf(x23.x + y23.x + bb.z, 0.f);
            a1w += fmaxf(x23.y + y23.y + bb.w, 0.f);
        }
        {
            const float2 x01 = __half22float2(*reinterpret_cast<const __half2*>(&pa1.x));
            const float2 x23 = __half22float2(*reinterpret_cast<const __half2*>(&pa1.y));
            const float2 y01 = __half22float2(*reinterpret_cast<const __half2*>(&pb1.x));
            const float2 y23 = __half22float2(*reinterpret_cast<const __half2*>(&pb1.y));
            a1x += fmaxf(x01.x + y01.x + bb.x, 0.f);
            a1y += fmaxf(x01.y + y01.y + bb.y, 0.f);
            a1z += fmaxf(x23.x + y23.x + bb.z, 0.f);
            a1w += fmaxf(x23.y + y23.y + bb.w, 0.f);
        }
    }
    for (; i1 < s1b; i1++) {
        const int2 e0 = __ldg(g_sab + i1);
        const uint2 pa0 = *reinterpret_cast<const uint2*>(g_xwnh + (size_t)e0.x * 128 + lane * 4);
        const uint2 pb0 = *reinterpret_cast<const uint2*>(g_xwnh + (size_t)e0.y * 128 + lane * 4);
        const float2 x01 = __half22float2(*reinterpret_cast<const __half2*>(&pa0.x));
        const float2 x23 = __half22float2(*reinterpret_cast<const __half2*>(&pa0.y));
        const float2 y01 = __half22float2(*reinterpret_cast<const __half2*>(&pb0.x));
        const float2 y23 = __half22float2(*reinterpret_cast<const __half2*>(&pb0.y));
        a1x += fmaxf(x01.x + y01.x + bb.x, 0.f);
        a1y += fmaxf(x01.y + y01.y + bb.y, 0.f);
        a1z += fmaxf(x23.x + y23.x + bb.z, 0.f);
        a1w += fmaxf(x23.y + y23.y + bb.w, 0.f);
    }

    *reinterpret_cast<float4*>(g_conv + (size_t)r0 * 128 + lane * 4) =
        make_float4(a0x, a0y, a0z, a0w);
    if (r1 != r0)
        *reinterpret_cast<float4*>(g_conv + (size_t)r1 * 128 + lane * 4) =
            make_float4(a1x, a1y, a1z, a1w);
}

// ---------------------------------------------------------------------------
// Phase 4: fused final dual GEMM + epilogue, 64-row chunks (R10 geometry).
// 16 warps: m-group = wid&3 (4x16 = 64 rows), n-group = wid>>2 (4x32 = 128
// cols, 4 nt per warp per W matrix). Full tile coverage.
// ---------------------------------------------------------------------------
#define FBL_OFF  0
#define FBF_OFF  TILE_BYTES
#define FA0_OFF  (2 * TILE_BYTES)
#define FA1_OFF  (2 * TILE_BYTES + FTILE_BYTES)
#define SMEM_F   (2 * TILE_BYTES + 2 * FTILE_BYTES)   // 104448 B

__global__ __launch_bounds__(512, 1)
void gemm_final_kernel(const float* __restrict__ b, float* __restrict__ out,
                       int nrows) {
    extern __shared__ __align__(16) char smem[];
    const uint32_t sb = smem_u32(smem);

    const int tid = threadIdx.x;
    const int ntiles = (nrows + 63) / 64;
    const int stride = gridDim.x;
    const uint32_t aoff[2] = { FA0_OFF, FA1_OFF };

    load_b_tile(smem + FBL_OFF, g_wth + 0 * 16384, tid);
    load_b_tile(smem + FBF_OFF, g_wth + 1 * 16384, tid);

    int tile0 = blockIdx.x;
    if (tile0 < ntiles) {
#pragma unroll
        for (int j = 0; j < 2; j++) {
            const int i = tid + j * 512;          // 64 rows x 16 chunks = 1024
            const int r = i >> 4, c = i & 15;
            const int gr = tile0 * 64 + r;
            if (gr < nrows)
                cp_async16(sb + aoff[0] + (uint32_t)(r * HPITCH_B + c * 16),
                           g_xh + (size_t)gr * 128 + c * 8);
        }
    }
    cp_commit();

    const int wid = tid >> 5, lane = tid & 31;
    const int g = lane >> 2, t = lane & 3;
    const int m_base = (wid & 3) * 16;
    const int n_base = (wid >> 2) * 32;

    int buf = 0;
    for (int tile = tile0; tile < ntiles; tile += stride, buf ^= 1) {
        const int nxt = tile + stride;
        if (nxt < ntiles) {
#pragma unroll
            for (int j = 0; j < 2; j++) {
                const int i = tid + j * 512;
                const int r = i >> 4, c = i & 15;
                const int gr = nxt * 64 + r;
                if (gr < nrows)
                    cp_async16(sb + aoff[buf ^ 1] + (uint32_t)(r * HPITCH_B + c * 16),
                               g_xh + (size_t)gr * 128 + c * 8);
            }
        }
        cp_commit();
        cp_wait1();
        __syncthreads();

        float accl[4][4], accf[4][4];
#pragma unroll
        for (int nt = 0; nt < 4; nt++)
#pragma unroll
            for (int j = 0; j < 4; j++) { accl[nt][j] = 0.f; accf[nt][j] = 0.f; }

        const char* ar  = smem + aoff[buf] + (m_base + g) * HPITCH_B + 4 * t;
        const char* brl = smem + FBL_OFF + (n_base + g) * HPITCH_B + 4 * t;
        const char* brf = smem + FBF_OFF + (n_base + g) * HPITCH_B + 4 * t;

#pragma unroll
        for (int ks = 0; ks < 8; ks++) {
            const int kb = ks * 32;
            const uint32_t a0 = *reinterpret_cast<const uint32_t*>(ar + kb);
            const uint32_t a1 = *reinterpret_cast<const uint32_t*>(ar + 8 * HPITCH_B + kb);
            const uint32_t a2 = *reinterpret_cast<const uint32_t*>(ar + kb + 16);
            const uint32_t a3 = *reinterpret_cast<const uint32_t*>(ar + 8 * HPITCH_B + kb + 16);
#pragma unroll
            for (int nt = 0; nt < 4; nt++) {
                const uint32_t bl0 = *reinterpret_cast<const uint32_t*>(brl + nt * 8 * HPITCH_B + kb);
                const uint32_t bl1 = *reinterpret_cast<const uint32_t*>(brl + nt * 8 * HPITCH_B + kb + 16);
                mma_f16(accl[nt], a0, a1, a2, a3, bl0, bl1);
                const uint32_t bf0 = *reinterpret_cast<const uint32_t*>(brf + nt * 8 * HPITCH_B + kb);
                const uint32_t bf1 = *reinterpret_cast<const uint32_t*>(brf + nt * 8 * HPITCH_B + kb + 16);
                mma_f16(accf[nt], a0, a1, a2, a3, bf0, bf1);
            }
        }

        const int r0 = tile * 64 + m_base + g;
        const int r1 = r0 + 8;
#pragma unroll
        for (int nt = 0; nt < 4; nt++) {
            const int col = n_base + nt * 8 + 2 * t;
            const float2 b2 = __ldg(reinterpret_cast<const float2*>(b + col));
            if (r0 < nrows) {
                const float2 cv = *reinterpret_cast<const float2*>(g_conv + (size_t)r0 * 128 + col);
                float2 o;
                o.x = fmaxf(fmaf(accf[nt][0], cv.x, accl[nt][0]) + b2.x, 0.f);
                o.y = fmaxf(fmaf(accf[nt][1], cv.y, accl[nt][1]) + b2.y, 0.f);
                *reinterpret_cast<float2*>(out + (size_t)r0 * 128 + col) = o;
            }
            if (r1 < nrows) {
                const float2 cv = *reinterpret_cast<const float2*>(g_conv + (size_t)r1 * 128 + col);
                float2 o;
                o.x = fmaxf(fmaf(accf[nt][2], cv.x, accl[nt][2]) + b2.x, 0.f);
                o.y = fmaxf(fmaf(accf[nt][3], cv.y, accl[nt][3]) + b2.y, 0.f);
                *reinterpret_cast<float2*>(out + (size_t)r1 * 128 + col) = o;
            }
        }
        __syncthreads();
    }
}

// ---------------------------------------------------------------------------
extern "C" void kernel_launch(void* const* d_in, const int* in_sizes, int n_in,
                              void* d_out, int out_size) {
    const float* X  = (const float*)d_in[0];
    const int*   ra = (const int*)d_in[1];
    const int*   rb = (const int*)d_in[2];
    const int*   br = (const int*)d_in[3];
    const float* Wl = (const float*)d_in[4];
    const float* Wf = (const float*)d_in[5];
    const float* Wn = (const float*)d_in[6];
    const float* b  = (const float*)d_in[7];
    const float* bn = (const float*)d_in[8];
    float* out = (float*)d_out;

    const int n = in_sizes[0] / 128;   // 200000
    const int m = in_sizes[1];         // 2000000

    static bool attr_done = false;
    if (!attr_done) {
        cudaFuncSetAttribute(gemm_xwn_kernel,
                             cudaFuncAttributeMaxDynamicSharedMemorySize, SMEM_X);
        cudaFuncSetAttribute(gemm_final_kernel,
                             cudaFuncAttributeMaxDynamicSharedMemorySize, SMEM_F);
        attr_done = true;
    }

    prep_w_kernel<<<3, 256>>>(Wl, Wf, Wn);
    prep_x_kernel<<<(n * 32 + 255) / 256, 256>>>(X, n * 32);

    // Counting sort of edges by destination row
    hist_zero_kernel<<<(HPAD + 255) / 256, 256>>>();
    hist_kernel<<<1024, 256>>>(br, m);
    scan1_kernel<<<NBLK, 256>>>();
    scan2_kernel<<<1, 256>>>();
    scan3_kernel<<<(n + 256) / 256, 256>>>(n, m);
    scatter_kernel<<<(m + 255) / 256, 256>>>(ra, rb, br, m);

    gemm_xwn_kernel<<<148, 512, SMEM_X>>>(n);
    conv_row_kernel<<<(n + 15) / 16, 256>>>(bn, n);
    gemm_final_kernel<<<148, 512, SMEM_F>>>(b, out, n);
}

// round 14
// speedup vs baseline: 1.4168x; 1.0452x over previous
#include <cuda_runtime.h>
#include <cuda_fp16.h>
#include <cstdint>
#include <cstddef>

// ---------------------------------------------------------------------------
// WL2 graph conv layer — fp16 mma.sync (m16n8k16, fp32 accum) GEMMs +
// counting-sorted gather conv (2 rows/warp) + side-stream sort overlap.
//   main stream : prep_w -> prep_x -> gemm_xwn --------\
//   side stream : hist_zero -> hist -> scans -> scatter -+-> conv_row -> final
// R14 = R13 (313.5us) + the fork/join overlap as the ONLY change.
// ---------------------------------------------------------------------------

#define NMAX   200000
#define MEDGE  2000000
#define HPAD   200704              // 196 * 1024 (padded histogram length)
#define NBLK   196                 // scan blocks of 1024
#define MAXELEMS ((size_t)NMAX * 128)

__device__ __half g_xh[MAXELEMS];        // fp16 copy of X
__device__ __half g_xwnh[MAXELEMS];      // fp16 neighbor projection
__device__ float  g_conv[MAXELEMS];      // conv rows (written once, no atomics)
__device__ __half g_wth[3 * 128 * 128];  // W^T (K-major), fp16

__device__ int  g_hist[HPAD];
__device__ int  g_rowscan[HPAD];
__device__ int  g_bsum[NBLK];
__device__ int  g_bsumoff[NBLK];
__device__ int  g_rowstart[NMAX + 1];
__device__ int  g_cursor[NMAX];
__device__ int2 g_sab[MEDGE];            // sorted (ref_a, ref_b) pairs

// ---------------- helpers ----------------
__device__ __forceinline__ uint32_t smem_u32(const void* p) {
    uint32_t a;
    asm("{ .reg .u64 t; cvta.to.shared.u64 t, %1; cvt.u32.u64 %0, t; }"
        : "=r"(a) : "l"(p));
    return a;
}

__device__ __forceinline__ void cp_async16(uint32_t dst, const void* src) {
    asm volatile("cp.async.ca.shared.global [%0], [%1], 16;"
                 :: "r"(dst), "l"(src) : "memory");
}
__device__ __forceinline__ void cp_commit() {
    asm volatile("cp.async.commit_group;" ::: "memory");
}
__device__ __forceinline__ void cp_wait1() {
    asm volatile("cp.async.wait_group 1;" ::: "memory");
}

// fp16 mma with fp32 accumulators: D = A(16x16,row) * B(16x8,col) + D
__device__ __forceinline__ void mma_f16(float* c,
                                        uint32_t a0, uint32_t a1, uint32_t a2, uint32_t a3,
                                        uint32_t b0, uint32_t b1) {
    asm volatile(
        "mma.sync.aligned.m16n8k16.row.col.f32.f16.f16.f32 "
        "{%0,%1,%2,%3}, {%4,%5,%6,%7}, {%8,%9}, {%0,%1,%2,%3};"
        : "+f"(c[0]), "+f"(c[1]), "+f"(c[2]), "+f"(c[3])
        : "r"(a0), "r"(a1), "r"(a2), "r"(a3), "r"(b0), "r"(b1));
}

// smem tile geometry: rows of 128 halves padded to 136 (272 B, 16B-aligned,
// 68 words == 4 mod 32 -> all fragment loads bank-conflict-free).
#define HPITCH_B    272                   // bytes per padded row
#define TILE_BYTES  (128 * HPITCH_B)      // 34816 B per 128-row tile
#define FTILE_BYTES (64 * HPITCH_B)       // 17408 B per 64-row A tile

// ---------------------------------------------------------------------------
// Phase 0a: W^T -> fp16
// ---------------------------------------------------------------------------
__global__ void prep_w_kernel(const float* __restrict__ Wl,
                              const float* __restrict__ Wf,
                              const float* __restrict__ Wn) {
    const float* src = (blockIdx.x == 0) ? Wl : ((blockIdx.x == 1) ? Wf : Wn);
    __half* dst = g_wth + blockIdx.x * 16384;
    for (int i = threadIdx.x; i < 16384; i += blockDim.x) {
        int n = i >> 7, k = i & 127;
        dst[i] = __float2half_rn(src[k * 128 + n]);   // [n][k]
    }
}

// ---------------------------------------------------------------------------
// Phase 0b: X -> fp16
// ---------------------------------------------------------------------------
__global__ void prep_x_kernel(const float* __restrict__ X, int total4) {
    const int i = blockIdx.x * 256 + threadIdx.x;
    if (i >= total4) return;
    const float4 v = reinterpret_cast<const float4*>(X)[i];
    const __half2 h0 = __floats2half2_rn(v.x, v.y);
    const __half2 h1 = __floats2half2_rn(v.z, v.w);
    uint2 o;
    o.x = *reinterpret_cast<const uint32_t*>(&h0);
    o.y = *reinterpret_cast<const uint32_t*>(&h1);
    reinterpret_cast<uint2*>(g_xh)[i] = o;
}

// ---------------------------------------------------------------------------
// Phase 1 (side stream): counting sort of edges by backref
// ---------------------------------------------------------------------------
__global__ void hist_zero_kernel() {
    int i = blockIdx.x * 256 + threadIdx.x;
    if (i < HPAD) g_hist[i] = 0;
}

__global__ void hist_kernel(const int* __restrict__ br, int m) {
    for (int e = blockIdx.x * 256 + threadIdx.x; e < m; e += gridDim.x * 256)
        atomicAdd(&g_hist[__ldg(br + e)], 1);
}

__global__ void scan1_kernel() {
    __shared__ int wsum[8];
    const int t = threadIdx.x;
    const int base = blockIdx.x * 1024 + t * 4;
    const int4 v = *reinterpret_cast<const int4*>(g_hist + base);
    const int s1 = v.x + v.y, s2 = s1 + v.z, s3 = s2 + v.w;
    const int lane = t & 31, w = t >> 5;
    int x = s3;
#pragma unroll
    for (int d = 1; d < 32; d <<= 1) {
        int y = __shfl_up_sync(0xffffffffu, x, d);
        if (lane >= d) x += y;
    }
    if (lane == 31) wsum[w] = x;
    __syncthreads();
    if (t < 8) {
        int v2 = wsum[t];
#pragma unroll
        for (int d = 1; d < 8; d <<= 1) {
            int y = __shfl_up_sync(0xffu, v2, d);
            if (t >= d) v2 += y;
        }
        wsum[t] = v2;
    }
    __syncthreads();
    const int woff = w ? wsum[w - 1] : 0;
    const int excl = woff + x - s3;
    int4 o;
    o.x = excl; o.y = excl + v.x; o.z = excl + s1; o.w = excl + s2;
    *reinterpret_cast<int4*>(g_rowscan + base) = o;
    if (t == 255) g_bsum[blockIdx.x] = wsum[7];
}

__global__ void scan2_kernel() {
    __shared__ int wsum[8];
    const int t = threadIdx.x;
    const int v = (t < NBLK) ? g_bsum[t] : 0;
    const int lane = t & 31, w = t >> 5;
    int x = v;
#pragma unroll
    for (int d = 1; d < 32; d <<= 1) {
        int y = __shfl_up_sync(0xffffffffu, x, d);
        if (lane >= d) x += y;
    }
    if (lane == 31) wsum[w] = x;
    __syncthreads();
    if (t < 8) {
        int v2 = wsum[t];
#pragma unroll
        for (int d = 1; d < 8; d <<= 1) {
            int y = __shfl_up_sync(0xffu, v2, d);
            if (t >= d) v2 += y;
        }
        wsum[t] = v2;
    }
    __syncthreads();
    const int woff = w ? wsum[w - 1] : 0;
    if (t < NBLK) g_bsumoff[t] = woff + x - v;
}

__global__ void scan3_kernel(int n, int m) {
    const int i = blockIdx.x * 256 + threadIdx.x;
    if (i < n) {
        const int val = g_rowscan[i] + g_bsumoff[i >> 10];
        g_rowstart[i] = val;
        g_cursor[i] = val;
    }
    if (i == 0) g_rowstart[n] = m;
}

__global__ void scatter_kernel(const int* __restrict__ ra,
                               const int* __restrict__ rb,
                               const int* __restrict__ br, int m) {
    const int e = blockIdx.x * 256 + threadIdx.x;
    if (e >= m) return;
    const int c = __ldg(br + e);
    const int p = atomicAdd(&g_cursor[c], 1);
    g_sab[p] = make_int2(__ldg(ra + e), __ldg(rb + e));
}

// ---------------------------------------------------------------------------
// B-tile loader: g_wth [n][k] fp16 -> smem padded rows. 512 threads.
// ---------------------------------------------------------------------------
__device__ __forceinline__ void load_b_tile(char* dst, const __half* __restrict__ Wt,
                                            int tid) {
    for (int i = tid; i < 2048; i += 512) {
        const int r = i >> 4, c = i & 15;
        const uint4 v = *reinterpret_cast<const uint4*>(Wt + r * 128 + c * 8);
        *reinterpret_cast<uint4*>(dst + r * HPITCH_B + c * 16) = v;
    }
}

// ---------------------------------------------------------------------------
// Phase 2: XW_n = X @ W_n, persistent; 128-row chunks, double-buffered A.
// 16 warps: m-group = wid&7 (16 rows), n-group = wid>>3 (64 cols, 8 nt).
// ---------------------------------------------------------------------------
#define XB_OFF   0
#define XA0_OFF  TILE_BYTES
#define XA1_OFF  (2 * TILE_BYTES)
#define SMEM_X   (3 * TILE_BYTES)      // 104448 B

__global__ __launch_bounds__(512, 1)
void gemm_xwn_kernel(int nrows) {
    extern __shared__ __align__(16) char smem[];
    const uint32_t sb = smem_u32(smem);

    const int tid = threadIdx.x;
    const int ntiles = (nrows + 127) / 128;
    const int stride = gridDim.x;
    const uint32_t aoff[2] = { XA0_OFF, XA1_OFF };

    load_b_tile(smem + XB_OFF, g_wth + 2 * 16384, tid);

    int tile0 = blockIdx.x;
    if (tile0 < ntiles) {
#pragma unroll
        for (int j = 0; j < 4; j++) {
            const int i = tid + j * 512;
            const int r = i >> 4, c = i & 15;
            const int gr = tile0 * 128 + r;
            if (gr < nrows)
                cp_async16(sb + aoff[0] + (uint32_t)(r * HPITCH_B + c * 16),
                           g_xh + (size_t)gr * 128 + c * 8);
        }
    }
    cp_commit();

    const int wid = tid >> 5, lane = tid & 31;
    const int g = lane >> 2, t = lane & 3;
    const int m_base = (wid & 7) * 16;
    const int n_base = (wid >> 3) * 64;

    int buf = 0;
    for (int tile = tile0; tile < ntiles; tile += stride, buf ^= 1) {
        const int nxt = tile + stride;
        if (nxt < ntiles) {
#pragma unroll
            for (int j = 0; j < 4; j++) {
                const int i = tid + j * 512;
                const int r = i >> 4, c = i & 15;
                const int gr = nxt * 128 + r;
                if (gr < nrows)
                    cp_async16(sb + aoff[buf ^ 1] + (uint32_t)(r * HPITCH_B + c * 16),
                               g_xh + (size_t)gr * 128 + c * 8);
            }
        }
        cp_commit();
        cp_wait1();
        __syncthreads();

        float acc[8][4];
#pragma unroll
        for (int nt = 0; nt < 8; nt++)
#pragma unroll
            for (int j = 0; j < 4; j++) acc[nt][j] = 0.f;

        const char* ar = smem + aoff[buf] + (m_base + g) * HPITCH_B + 4 * t;
        const char* br = smem + XB_OFF + (n_base + g) * HPITCH_B + 4 * t;

#pragma unroll
        for (int ks = 0; ks < 8; ks++) {
            const int kb = ks * 32;   // 16 halves = 32 bytes per K-step
            const uint32_t a0 = *reinterpret_cast<const uint32_t*>(ar + kb);
            const uint32_t a1 = *reinterpret_cast<const uint32_t*>(ar + 8 * HPITCH_B + kb);
            const uint32_t a2 = *reinterpret_cast<const uint32_t*>(ar + kb + 16);
            const uint32_t a3 = *reinterpret_cast<const uint32_t*>(ar + 8 * HPITCH_B + kb + 16);
#pragma unroll
            for (int nt = 0; nt < 8; nt++) {
                const uint32_t b0 = *reinterpret_cast<const uint32_t*>(br + nt * 8 * HPITCH_B + kb);
                const uint32_t b1 = *reinterpret_cast<const uint32_t*>(br + nt * 8 * HPITCH_B + kb + 16);
                mma_f16(acc[nt], a0, a1, a2, a3, b0, b1);
            }
        }

        const int r0 = tile * 128 + m_base + g;
        const int r1 = r0 + 8;
#pragma unroll
        for (int nt = 0; nt < 8; nt++) {
            const int col = n_base + nt * 8 + 2 * t;
            if (r0 < nrows)
                *reinterpret_cast<__half2*>(g_xwnh + (size_t)r0 * 128 + col) =
                    __floats2half2_rn(acc[nt][0], acc[nt][1]);
            if (r1 < nrows)
                *reinterpret_cast<__half2*>(g_xwnh + (size_t)r1 * 128 + col) =
                    __floats2half2_rn(acc[nt][2], acc[nt][3]);
        }
        __syncthreads();
    }
}

// ---------------------------------------------------------------------------
// Phase 3: conv rows. One warp per TWO rows (interleaved gathers for MLP);
// register sum, single coalesced store per row.
// ---------------------------------------------------------------------------
__global__ __launch_bounds__(256)
void conv_row_kernel(const float* __restrict__ bn, int n) {
    const int wid = threadIdx.x >> 5, lane = threadIdx.x & 31;
    const int r0 = (blockIdx.x * 8 + wid) * 2;
    if (r0 >= n) return;
    const int r1 = (r0 + 1 < n) ? (r0 + 1) : r0;

    const int s0a = g_rowstart[r0];
    const int s0b = g_rowstart[r0 + 1];
    const int s1a = (r1 != r0) ? g_rowstart[r1] : s0a;
    const int s1b = (r1 != r0) ? g_rowstart[r1 + 1] : s0a;

    const float4 bb = __ldg(reinterpret_cast<const float4*>(bn) + lane);

    float a0x = 0.f, a0y = 0.f, a0z = 0.f, a0w = 0.f;
    float a1x = 0.f, a1y = 0.f, a1z = 0.f, a1w = 0.f;

    int i0 = s0a, i1 = s1a;
    while (i0 < s0b && i1 < s1b) {
        const int2 e0 = __ldg(g_sab + i0);
        const int2 e1 = __ldg(g_sab + i1);
        const uint2 pa0 = *reinterpret_cast<const uint2*>(g_xwnh + (size_t)e0.x * 128 + lane * 4);
        const uint2 pb0 = *reinterpret_cast<const uint2*>(g_xwnh + (size_t)e0.y * 128 + lane * 4);
        const uint2 pa1 = *reinterpret_cast<const uint2*>(g_xwnh + (size_t)e1.x * 128 + lane * 4);
        const uint2 pb1 = *reinterpret_cast<const uint2*>(g_xwnh + (size_t)e1.y * 128 + lane * 4);
        {
            const float2 x01 = __half22float2(*reinterpret_cast<const __half2*>(&pa0.x));
            const float2 x23 = __half22float2(*reinterpret_cast<const __half2*>(&pa0.y));
            const float2 y01 = __half22float2(*reinterpret_cast<const __half2*>(&pb0.x));
            const float2 y23 = __half22float2(*reinterpret_cast<const __half2*>(&pb0.y));
            a0x += fmaxf(x01.x + y01.x + bb.x, 0.f);
            a0y += fmaxf(x01.y + y01.y + bb.y, 0.f);
            a0z += fmaxf(x23.x + y23.x + bb.z, 0.f);
            a0w += fmaxf(x23.y + y23.y + bb.w, 0.f);
        }
        {
            const float2 x01 = __half22float2(*reinterpret_cast<const __half2*>(&pa1.x));
            const float2 x23 = __half22float2(*reinterpret_cast<const __half2*>(&pa1.y));
            const float2 y01 = __half22float2(*reinterpret_cast<const __half2*>(&pb1.x));
            const float2 y23 = __half22float2(*reinterpret_cast<const __half2*>(&pb1.y));
            a1x += fmaxf(x01.x + y01.x + bb.x, 0.f);
            a1y += fmaxf(x01.y + y01.y + bb.y, 0.f);
            a1z += fmaxf(x23.x + y23.x + bb.z, 0.f);
            a1w += fmaxf(x23.y + y23.y + bb.w, 0.f);
        }
        i0++; i1++;
    }
    for (; i0 + 2 <= s0b; i0 += 2) {
        const int2 e0 = __ldg(g_sab + i0);
        const int2 e1 = __ldg(g_sab + i0 + 1);
        const uint2 pa0 = *reinterpret_cast<const uint2*>(g_xwnh + (size_t)e0.x * 128 + lane * 4);
        const uint2 pb0 = *reinterpret_cast<const uint2*>(g_xwnh + (size_t)e0.y * 128 + lane * 4);
        const uint2 pa1 = *reinterpret_cast<const uint2*>(g_xwnh + (size_t)e1.x * 128 + lane * 4);
        const uint2 pb1 = *reinterpret_cast<const uint2*>(g_xwnh + (size_t)e1.y * 128 + lane * 4);
        {
            const float2 x01 = __half22float2(*reinterpret_cast<const __half2*>(&pa0.x));
            const float2 x23 = __half22float2(*reinterpret_cast<const __half2*>(&pa0.y));
            const float2 y01 = __half22float2(*reinterpret_cast<const __half2*>(&pb0.x));
            const float2 y23 = __half22float2(*reinterpret_cast<const __half2*>(&pb0.y));
            a0x += fmaxf(x01.x + y01.x + bb.x, 0.f);
            a0y += fmaxf(x01.y + y01.y + bb.y, 0.f);
            a0z += fmaxf(x23.x + y23.x + bb.z, 0.f);
            a0w += fmaxf(x23.y + y23.y + bb.w, 0.f);
        }
        {
            const float2 x01 = __half22float2(*reinterpret_cast<const __half2*>(&pa1.x));
            const float2 x23 = __half22float2(*reinterpret_cast<const __half2*>(&pa1.y));
            const float2 y01 = __half22float2(*reinterpret_cast<const __half2*>(&pb1.x));
            const float2 y23 = __half22float2(*reinterpret_cast<const __half2*>(&pb1.y));
            a0x += fmaxf(x01.x + y01.x + bb.x, 0.f);
            a0y += fmaxf(x01.y + y01.y + bb.y, 0.f);
            a0z += fmaxf(x23.x + y23.x + bb.z, 0.f);
            a0w += fmaxf(x23.y + y23.y + bb.w, 0.f);
        }
    }
    for (; i0 < s0b; i0++) {
        const int2 e0 = __ldg(g_sab + i0);
        const uint2 pa0 = *reinterpret_cast<const uint2*>(g_xwnh + (size_t)e0.x * 128 + lane * 4);
        const uint2 pb0 = *reinterpret_cast<const uint2*>(g_xwnh + (size_t)e0.y * 128 + lane * 4);
        const float2 x01 = __half22float2(*reinterpret_cast<const __half2*>(&pa0.x));
        const float2 x23 = __half22float2(*reinterpret_cast<const __half2*>(&pa0.y));
        const float2 y01 = __half22float2(*reinterpret_cast<const __half2*>(&pb0.x));
        const float2 y23 = __half22float2(*reinterpret_cast<const __half2*>(&pb0.y));
        a0x += fmaxf(x01.x + y01.x + bb.x, 0.f);
        a0y += fmaxf(x01.y + y01.y + bb.y, 0.f);
        a0z += fmaxf(x23.x + y23.x + bb.z, 0.f);
        a0w += fmaxf(x23.y + y23.y + bb.w, 0.f);
    }
    for (; i1 + 2 <= s1b; i1 += 2) {
        const int2 e0 = __ldg(g_sab + i1);
        const int2 e1 = __ldg(g_sab + i1 + 1);
        const uint2 pa0 = *reinterpret_cast<const uint2*>(g_xwnh + (size_t)e0.x * 128 + lane * 4);
        const uint2 pb0 = *reinterpret_cast<const uint2*>(g_xwnh + (size_t)e0.y * 128 + lane * 4);
        const uint2 pa1 = *reinterpret_cast<const uint2*>(g_xwnh + (size_t)e1.x * 128 + lane * 4);
        const uint2 pb1 = *reinterpret_cast<const uint2*>(g_xwnh + (size_t)e1.y * 128 + lane * 4);
        {
            const float2 x01 = __half22float2(*reinterpret_cast<const __half2*>(&pa0.x));
            const float2 x23 = __half22float2(*reinterpret_cast<const __half2*>(&pa0.y));
            const float2 y01 = __half22float2(*reinterpret_cast<const __half2*>(&pb0.x));
            const float2 y23 = __half22float2(*reinterpret_cast<const __half2*>(&pb0.y));
            a1x += fmaxf(x01.x + y01.x + bb.x, 0.f);
            a1y += fmaxf(x01.y + y01.y + bb.y, 0.f);
            a1z += fmaxf(x23.x + y23.x + bb.z, 0.f);
            a1w += fmaxf(x23.y + y23.y + bb.w, 0.f);
        }
        {
            const float2 x01 = __half22float2(*reinterpret_cast<const __half2*>(&pa1.x));
            const float2 x23 = __half22float2(*reinterpret_cast<const __half2*>(&pa1.y));
            const float2 y01 = __half22float2(*reinterpret_cast<const __half2*>(&pb1.x));
            const float2 y23 = __half22float2(*reinterpret_cast<const __half2*>(&pb1.y));
            a1x += fmaxf(x01.x + y01.x + bb.x, 0.f);
            a1y += fmaxf(x01.y + y01.y + bb.y, 0.f);
            a1z += fmaxf(x23.x + y23.x + bb.z, 0.f);
            a1w += fmaxf(x23.y + y23.y + bb.w, 0.f);
        }
    }
    for (; i1 < s1b; i1++) {
        const int2 e0 = __ldg(g_sab + i1);
        const uint2 pa0 = *reinterpret_cast<const uint2*>(g_xwnh + (size_t)e0.x * 128 + lane * 4);
        const uint2 pb0 = *reinterpret_cast<const uint2*>(g_xwnh + (size_t)e0.y * 128 + lane * 4);
        const float2 x01 = __half22float2(*reinterpret_cast<const __half2*>(&pa0.x));
        const float2 x23 = __half22float2(*reinterpret_cast<const __half2*>(&pa0.y));
        const float2 y01 = __half22float2(*reinterpret_cast<const __half2*>(&pb0.x));
        const float2 y23 = __half22float2(*reinterpret_cast<const __half2*>(&pb0.y));
        a1x += fmaxf(x01.x + y01.x + bb.x, 0.f);
        a1y += fmaxf(x01.y + y01.y + bb.y, 0.f);
        a1z += fmaxf(x23.x + y23.x + bb.z, 0.f);
        a1w += fmaxf(x23.y + y23.y + bb.w, 0.f);
    }

    *reinterpret_cast<float4*>(g_conv + (size_t)r0 * 128 + lane * 4) =
        make_float4(a0x, a0y, a0z, a0w);
    if (r1 != r0)
        *reinterpret_cast<float4*>(g_conv + (size_t)r1 * 128 + lane * 4) =
            make_float4(a1x, a1y, a1z, a1w);
}

// ---------------------------------------------------------------------------
// Phase 4: fused final dual GEMM + epilogue, 64-row chunks.
// 16 warps: m-group = wid&3 (4x16 = 64 rows), n-group = wid>>2 (4x32 = 128
// cols, 4 nt per warp per W matrix). Full tile coverage.
// ---------------------------------------------------------------------------
#define FBL_OFF  0
#define FBF_OFF  TILE_BYTES
#define FA0_OFF  (2 * TILE_BYTES)
#define FA1_OFF  (2 * TILE_BYTES + FTILE_BYTES)
#define SMEM_F   (2 * TILE_BYTES + 2 * FTILE_BYTES)   // 104448 B

__global__ __launch_bounds__(512, 1)
void gemm_final_kernel(const float* __restrict__ b, float* __restrict__ out,
                       int nrows) {
    extern __shared__ __align__(16) char smem[];
    const uint32_t sb = smem_u32(smem);

    const int tid = threadIdx.x;
    const int ntiles = (nrows + 63) / 64;
    const int stride = gridDim.x;
    const uint32_t aoff[2] = { FA0_OFF, FA1_OFF };

    load_b_tile(smem + FBL_OFF, g_wth + 0 * 16384, tid);
    load_b_tile(smem + FBF_OFF, g_wth + 1 * 16384, tid);

    int tile0 = blockIdx.x;
    if (tile0 < ntiles) {
#pragma unroll
        for (int j = 0; j < 2; j++) {
            const int i = tid + j * 512;          // 64 rows x 16 chunks = 1024
            const int r = i >> 4, c = i & 15;
            const int gr = tile0 * 64 + r;
            if (gr < nrows)
                cp_async16(sb + aoff[0] + (uint32_t)(r * HPITCH_B + c * 16),
                           g_xh + (size_t)gr * 128 + c * 8);
        }
    }
    cp_commit();

    const int wid = tid >> 5, lane = tid & 31;
    const int g = lane >> 2, t = lane & 3;
    const int m_base = (wid & 3) * 16;
    const int n_base = (wid >> 2) * 32;

    int buf = 0;
    for (int tile = tile0; tile < ntiles; tile += stride, buf ^= 1) {
        const int nxt = tile + stride;
        if (nxt < ntiles) {
#pragma unroll
            for (int j = 0; j < 2; j++) {
                const int i = tid + j * 512;
                const int r = i >> 4, c = i & 15;
                const int gr = nxt * 64 + r;
                if (gr < nrows)
                    cp_async16(sb + aoff[buf ^ 1] + (uint32_t)(r * HPITCH_B + c * 16),
                               g_xh + (size_t)gr * 128 + c * 8);
            }
        }
        cp_commit();
        cp_wait1();
        __syncthreads();

        float accl[4][4], accf[4][4];
#pragma unroll
        for (int nt = 0; nt < 4; nt++)
#pragma unroll
            for (int j = 0; j < 4; j++) { accl[nt][j] = 0.f; accf[nt][j] = 0.f; }

        const char* ar  = smem + aoff[buf] + (m_base + g) * HPITCH_B + 4 * t;
        const char* brl = smem + FBL_OFF + (n_base + g) * HPITCH_B + 4 * t;
        const char* brf = smem + FBF_OFF + (n_base + g) * HPITCH_B + 4 * t;

#pragma unroll
        for (int ks = 0; ks < 8; ks++) {
            const int kb = ks * 32;
            const uint32_t a0 = *reinterpret_cast<const uint32_t*>(ar + kb);
            const uint32_t a1 = *reinterpret_cast<const uint32_t*>(ar + 8 * HPITCH_B + kb);
            const uint32_t a2 = *reinterpret_cast<const uint32_t*>(ar + kb + 16);
            const uint32_t a3 = *reinterpret_cast<const uint32_t*>(ar + 8 * HPITCH_B + kb + 16);
#pragma unroll
            for (int nt = 0; nt < 4; nt++) {
                const uint32_t bl0 = *reinterpret_cast<const uint32_t*>(brl + nt * 8 * HPITCH_B + kb);
                const uint32_t bl1 = *reinterpret_cast<const uint32_t*>(brl + nt * 8 * HPITCH_B + kb + 16);
                mma_f16(accl[nt], a0, a1, a2, a3, bl0, bl1);
                const uint32_t bf0 = *reinterpret_cast<const uint32_t*>(brf + nt * 8 * HPITCH_B + kb);
                const uint32_t bf1 = *reinterpret_cast<const uint32_t*>(brf + nt * 8 * HPITCH_B + kb + 16);
                mma_f16(accf[nt], a0, a1, a2, a3, bf0, bf1);
            }
        }

        const int r0 = tile * 64 + m_base + g;
        const int r1 = r0 + 8;
#pragma unroll
        for (int nt = 0; nt < 4; nt++) {
            const int col = n_base + nt * 8 + 2 * t;
            const float2 b2 = __ldg(reinterpret_cast<const float2*>(b + col));
            if (r0 < nrows) {
                const float2 cv = *reinterpret_cast<const float2*>(g_conv + (size_t)r0 * 128 + col);
                float2 o;
                o.x = fmaxf(fmaf(accf[nt][0], cv.x, accl[nt][0]) + b2.x, 0.f);
                o.y = fmaxf(fmaf(accf[nt][1], cv.y, accl[nt][1]) + b2.y, 0.f);
                *reinterpret_cast<float2*>(out + (size_t)r0 * 128 + col) = o;
            }
            if (r1 < nrows) {
                const float2 cv = *reinterpret_cast<const float2*>(g_conv + (size_t)r1 * 128 + col);
                float2 o;
                o.x = fmaxf(fmaf(accf[nt][2], cv.x, accl[nt][2]) + b2.x, 0.f);
                o.y = fmaxf(fmaf(accf[nt][3], cv.y, accl[nt][3]) + b2.y, 0.f);
                *reinterpret_cast<float2*>(out + (size_t)r1 * 128 + col) = o;
            }
        }
        __syncthreads();
    }
}

// ---------------------------------------------------------------------------
extern "C" void kernel_launch(void* const* d_in, const int* in_sizes, int n_in,
                              void* d_out, int out_size) {
    const float* X  = (const float*)d_in[0];
    const int*   ra = (const int*)d_in[1];
    const int*   rb = (const int*)d_in[2];
    const int*   br = (const int*)d_in[3];
    const float* Wl = (const float*)d_in[4];
    const float* Wf = (const float*)d_in[5];
    const float* Wn = (const float*)d_in[6];
    const float* b  = (const float*)d_in[7];
    const float* bn = (const float*)d_in[8];
    float* out = (float*)d_out;

    const int n = in_sizes[0] / 128;   // 200000
    const int m = in_sizes[1];         // 2000000

    static cudaStream_t s_side = nullptr;
    static cudaEvent_t ev_fork, ev_join;
    static bool init_done = false;
    if (!init_done) {
        cudaFuncSetAttribute(gemm_xwn_kernel,
                             cudaFuncAttributeMaxDynamicSharedMemorySize, SMEM_X);
        cudaFuncSetAttribute(gemm_final_kernel,
                             cudaFuncAttributeMaxDynamicSharedMemorySize, SMEM_F);
        cudaStreamCreateWithFlags(&s_side, cudaStreamNonBlocking);
        cudaEventCreateWithFlags(&ev_fork, cudaEventDisableTiming);
        cudaEventCreateWithFlags(&ev_join, cudaEventDisableTiming);
        init_done = true;
    }

    // Fork: counting sort on the side stream, concurrent with fp16 prep +
    // the xwn GEMM on the main (capture-origin) stream.
    cudaEventRecord(ev_fork, 0);
    cudaStreamWaitEvent(s_side, ev_fork, 0);

    hist_zero_kernel<<<(HPAD + 255) / 256, 256, 0, s_side>>>();
    hist_kernel<<<1024, 256, 0, s_side>>>(br, m);
    scan1_kernel<<<NBLK, 256, 0, s_side>>>();
    scan2_kernel<<<1, 256, 0, s_side>>>();
    scan3_kernel<<<(n + 256) / 256, 256, 0, s_side>>>(n, m);
    scatter_kernel<<<(m + 255) / 256, 256, 0, s_side>>>(ra, rb, br, m);
    cudaEventRecord(ev_join, s_side);

    prep_w_kernel<<<3, 256>>>(Wl, Wf, Wn);
    prep_x_kernel<<<(n * 32 + 255) / 256, 256>>>(X, n * 32);
    gemm_xwn_kernel<<<148, 512, SMEM_X>>>(n);

    // Join: conv needs both the sorted edges and the xwn projection.
    cudaStreamWaitEvent(0, ev_join, 0);
    conv_row_kernel<<<(n + 15) / 16, 256>>>(bn, n);
    gemm_final_kernel<<<148, 512, SMEM_F>>>(b, out, n);
}